// round 4
// baseline (speedup 1.0000x reference)
#include <cuda_runtime.h>
#include <cuda_bf16.h>
#include <cstdint>
#include <math.h>

#define B_      256
#define FERD    2048
#define LMD     256
#define NC      7
#define KNN     8
#define NPAIR   (B_*KNN)     // 2048
#define EPSV    1e-8f

__device__ __forceinline__ uint32_t smem_to_u32(const void* p) {
    uint32_t a;
    asm("{ .reg .u64 t; cvta.to.shared.u64 t, %1; cvt.u32.u64 %0, t; }" : "=r"(a) : "l"(p));
    return a;
}

// ====================================================================
// scratch (no allocations allowed)
// ====================================================================
struct __align__(16) Scratch {
    // bf16 operands
    __nv_bfloat16 w_in_b[FERD*FERD];
    __nv_bfloat16 w1_b  [1024*FERD];
    __nv_bfloat16 w2_b  [512*1024];
    __nv_bfloat16 xhi_fer[B_*FERD];
    __nv_bfloat16 xlo_fer[B_*FERD];
    __nv_bfloat16 l_win_b[LMD*LMD];
    __nv_bfloat16 l_w1_b [128*LMD];
    __nv_bfloat16 xhi_lm [B_*LMD];
    __nv_bfloat16 xlo_lm [B_*LMD];
    __nv_bfloat16 feats_fer_b[B_*FERD];
    __nv_bfloat16 feats_lm_b [B_*LMD];
    __nv_bfloat16 H_fer_b[NPAIR*1024];
    __nv_bfloat16 H_lm_b [NPAIR*128];
    __nv_bfloat16 l_w2_pad_b[128*128];
    float         l_b2_pad[128];
    // fp32
    float G_fer[B_*B_], P_fer[B_*B_];
    float G_lm [B_*B_], P_lm [B_*B_];
    float A_fer[B_*1024], Bm_fer[B_*1024];
    float A_lm [B_*128],  Bm_lm [B_*128];
    float H2_fer[NPAIR*512];
    float H2_lm [NPAIR*128];     // padded N=128, only first 64 valid
    float score_fer[NPAIR], score_lm[NPAIR];
    int   nbr_fer[NPAIR], nbr_lm[NPAIR];
};
__device__ Scratch g_s;

// ====================================================================
// fp32 -> bf16 conversion of all tensor operands (with hi/lo split for x)
// ====================================================================
#define CN1 (FERD*FERD)
#define CN2 (1024*FERD)
#define CN3 (512*1024)
#define CN4 (B_*FERD)
#define CN5 (LMD*LMD)
#define CN6 (128*LMD)
#define CN7 (B_*LMD)
#define CTOT (CN1+CN2+CN3+CN4+CN5+CN6+CN7)
__global__ void convert_all(const float* __restrict__ fw_in, const float* __restrict__ fw1,
                            const float* __restrict__ fw2,  const float* __restrict__ fx,
                            const float* __restrict__ lwin, const float* __restrict__ lw1,
                            const float* __restrict__ lx,   Scratch* s) {
    int total4 = CTOT / 4;
    for (int i = blockIdx.x * blockDim.x + threadIdx.x; i < total4;
         i += gridDim.x * blockDim.x) {
        int j = i * 4;
        const float* src; __nv_bfloat16* dst; __nv_bfloat16* lo = nullptr; int off;
        if      (j < CN1)                     { src=fw_in; dst=s->w_in_b;  off=j; }
        else if (j < CN1+CN2)                 { src=fw1;   dst=s->w1_b;    off=j-CN1; }
        else if (j < CN1+CN2+CN3)             { src=fw2;   dst=s->w2_b;    off=j-CN1-CN2; }
        else if (j < CN1+CN2+CN3+CN4)         { src=fx;    dst=s->xhi_fer; lo=s->xlo_fer;
                                                off=j-CN1-CN2-CN3; }
        else if (j < CN1+CN2+CN3+CN4+CN5)     { src=lwin;  dst=s->l_win_b; off=j-CN1-CN2-CN3-CN4; }
        else if (j < CN1+CN2+CN3+CN4+CN5+CN6) { src=lw1;   dst=s->l_w1_b;  off=j-CN1-CN2-CN3-CN4-CN5; }
        else                                  { src=lx;    dst=s->xhi_lm;  lo=s->xlo_lm;
                                                off=j-CN1-CN2-CN3-CN4-CN5-CN6; }
        float4 v = *(const float4*)(src + off);
        __nv_bfloat16 h0 = __float2bfloat16(v.x), h1 = __float2bfloat16(v.y);
        __nv_bfloat16 h2 = __float2bfloat16(v.z), h3 = __float2bfloat16(v.w);
        *(__nv_bfloat162*)(dst + off)     = __nv_bfloat162(h0, h1);
        *(__nv_bfloat162*)(dst + off + 2) = __nv_bfloat162(h2, h3);
        if (lo) {
            *(__nv_bfloat162*)(lo + off) = __nv_bfloat162(
                __float2bfloat16(v.x - __bfloat162float(h0)),
                __float2bfloat16(v.y - __bfloat162float(h1)));
            *(__nv_bfloat162*)(lo + off + 2) = __nv_bfloat162(
                __float2bfloat16(v.z - __bfloat162float(h2)),
                __float2bfloat16(v.w - __bfloat162float(h3)));
        }
    }
}

// pad LM w2 (64x128) to 128x128 bf16, pad b2 to 128 with zeros
__global__ void prep_lm(const float* __restrict__ w2, const float* __restrict__ b2,
                        Scratch* s) {
    int t = blockIdx.x * blockDim.x + threadIdx.x;
    if (t < 128 * 128) {
        int r = t >> 7, c = t & 127;
        s->l_w2_pad_b[t] = __float2bfloat16(r < 64 ? w2[r * 128 + c] : 0.f);
    }
    if (t < 128) s->l_b2_pad[t] = (t < 64) ? b2[t] : 0.f;
}

// ====================================================================
// bf16 HMMA GEMM: C[M,N] = act(A(MxK,lda) . B(NxK,ldb)^T + bias)
// block tile 128x128, BK=64, 8 warps (2x4), mma.sync m16n8k16,
// cp.async double buffer. M,N multiple of 128, K multiple of 64.
// ====================================================================
#define MM_LDS   72
#define MM_ATILE (128*MM_LDS*2)
#define MM_BUF   (2*MM_ATILE)
#define MM_SMEM  (2*MM_BUF)

__global__ void __launch_bounds__(256)
gemm_mma(const __nv_bfloat16* __restrict__ A, int lda,
         const __nv_bfloat16* __restrict__ B, int ldb,
         const float* __restrict__ bias, int relu,
         float* __restrict__ Cf, __nv_bfloat16* __restrict__ Cb,
         int N, int K)
{
    extern __shared__ char smem[];
    uint32_t sb = smem_to_u32(smem);
    int tid = threadIdx.x;
    int lane = tid & 31, warp = tid >> 5;
    int wm = warp >> 2, wn = warp & 3;
    int m0 = blockIdx.y * 128, n0 = blockIdx.x * 128;

    float acc[4][4][4];
    #pragma unroll
    for (int i = 0; i < 4; i++)
        #pragma unroll
        for (int j = 0; j < 4; j++)
            #pragma unroll
            for (int q = 0; q < 4; q++) acc[i][j][q] = 0.f;

    int nk = K >> 6;

    auto issue = [&](int kt) {
        int s = kt & 1;
        uint32_t base = sb + s * MM_BUF;
        int k0 = kt * 64;
        #pragma unroll
        for (int u = 0; u < 4; u++) {
            int cc = tid * 4 + u;
            int row = cc >> 3;
            int col = (cc & 7) * 8;
            uint32_t da = base + (uint32_t)(row * MM_LDS + col) * 2;
            const __nv_bfloat16* ga = A + (size_t)(m0 + row) * lda + k0 + col;
            asm volatile("cp.async.cg.shared.global [%0], [%1], 16;" :: "r"(da), "l"(ga));
            const __nv_bfloat16* gb = B + (size_t)(n0 + row) * ldb + k0 + col;
            asm volatile("cp.async.cg.shared.global [%0], [%1], 16;"
                         :: "r"(da + MM_ATILE), "l"(gb));
        }
        asm volatile("cp.async.commit_group;" ::: "memory");
    };

    issue(0);
    for (int kt = 0; kt < nk; kt++) {
        if (kt + 1 < nk) {
            issue(kt + 1);
            asm volatile("cp.async.wait_group 1;" ::: "memory");
        } else {
            asm volatile("cp.async.wait_group 0;" ::: "memory");
        }
        __syncthreads();

        uint32_t aBase = sb + (kt & 1) * MM_BUF;
        uint32_t bBase = aBase + MM_ATILE;
        #pragma unroll
        for (int ks = 0; ks < 4; ks++) {
            int k = ks * 16;
            uint32_t af[4][4];
            #pragma unroll
            for (int im = 0; im < 4; im++) {
                int row = wm * 64 + im * 16 + (lane & 15);
                int kg = (lane >> 4) * 8;
                uint32_t addr = aBase + (uint32_t)(row * MM_LDS + k + kg) * 2;
                asm volatile("ldmatrix.sync.aligned.m8n8.x4.shared.b16 {%0,%1,%2,%3}, [%4];"
                             : "=r"(af[im][0]), "=r"(af[im][1]),
                               "=r"(af[im][2]), "=r"(af[im][3])
                             : "r"(addr));
            }
            uint32_t bf[4][2];
            #pragma unroll
            for (int in = 0; in < 4; in++) {
                int l = lane & 15;
                int n = wn * 32 + in * 8 + (l & 7);
                int kg = (l >> 3) * 8;
                uint32_t addr = bBase + (uint32_t)(n * MM_LDS + k + kg) * 2;
                asm volatile("ldmatrix.sync.aligned.m8n8.x2.shared.b16 {%0,%1}, [%2];"
                             : "=r"(bf[in][0]), "=r"(bf[in][1])
                             : "r"(addr));
            }
            #pragma unroll
            for (int im = 0; im < 4; im++)
                #pragma unroll
                for (int in = 0; in < 4; in++) {
                    asm volatile(
                        "mma.sync.aligned.m16n8k16.row.col.f32.bf16.bf16.f32 "
                        "{%0,%1,%2,%3}, {%4,%5,%6,%7}, {%8,%9}, {%0,%1,%2,%3};"
                        : "+f"(acc[im][in][0]), "+f"(acc[im][in][1]),
                          "+f"(acc[im][in][2]), "+f"(acc[im][in][3])
                        : "r"(af[im][0]), "r"(af[im][1]), "r"(af[im][2]), "r"(af[im][3]),
                          "r"(bf[in][0]), "r"(bf[in][1]));
                }
        }
        __syncthreads();
    }

    #pragma unroll
    for (int im = 0; im < 4; im++) {
        int m = m0 + wm * 64 + im * 16 + (lane >> 2);
        #pragma unroll
        for (int in = 0; in < 4; in++) {
            int n = n0 + wn * 32 + in * 8 + (lane & 3) * 2;
            float b0 = bias ? bias[n]     : 0.f;
            float b1 = bias ? bias[n + 1] : 0.f;
            float v00 = acc[im][in][0] + b0, v01 = acc[im][in][1] + b1;
            float v10 = acc[im][in][2] + b0, v11 = acc[im][in][3] + b1;
            if (relu) {
                v00 = fmaxf(v00, 0.f); v01 = fmaxf(v01, 0.f);
                v10 = fmaxf(v10, 0.f); v11 = fmaxf(v11, 0.f);
            }
            if (Cf) {
                *(float2*)(Cf + (size_t)m * N + n)       = make_float2(v00, v01);
                *(float2*)(Cf + (size_t)(m + 8) * N + n) = make_float2(v10, v11);
            } else {
                *(__nv_bfloat162*)(Cb + (size_t)m * N + n) =
                    __floats2bfloat162_rn(v00, v01);
                *(__nv_bfloat162*)(Cb + (size_t)(m + 8) * N + n) =
                    __floats2bfloat162_rn(v10, v11);
            }
        }
    }
}

// ====================================================================
// top-8 per row from split Gram matrices.
// sim-equivalent value: (G[i,j] + P[i,j] + P[j,i]) * rsqrt(G[j,j]+2P[j,j])
// (row scaling omitted — monotone). Strict >, lowest index wins ties.
// ====================================================================
__global__ void topk8_warp(const float* __restrict__ G, const float* __restrict__ P,
                           int* __restrict__ nbr) {
    int warp = blockIdx.x * (blockDim.x >> 5) + (threadIdx.x >> 5);
    int lane = threadIdx.x & 31;
    if (warp >= B_) return;
    float v[8];
    #pragma unroll
    for (int t = 0; t < 8; t++) {
        int j = lane + t * 32;
        if (j == warp) { v[t] = -1e30f; continue; }
        float g  = G[(size_t)warp * B_ + j];
        float p1 = P[(size_t)warp * B_ + j];
        float p2 = P[(size_t)j * B_ + warp];
        float dg = G[(size_t)j * B_ + j];
        float dp = P[(size_t)j * B_ + j];
        v[t] = (g + p1 + p2) * rsqrtf(dg + 2.f * dp);
    }
    for (int t = 0; t < KNN; t++) {
        float bv = -1e30f; int bi = 0x7fffffff;
        #pragma unroll
        for (int q = 0; q < 8; q++) {
            int j = lane + q * 32;
            if (v[q] > bv || (v[q] == bv && j < bi)) { bv = v[q]; bi = j; }
        }
        #pragma unroll
        for (int o = 16; o; o >>= 1) {
            float ov = __shfl_xor_sync(0xffffffffu, bv, o);
            int   oi = __shfl_xor_sync(0xffffffffu, bi, o);
            if (ov > bv || (ov == bv && oi < bi)) { bv = ov; bi = oi; }
        }
        if (lane == 0) nbr[warp * KNN + t] = bi;
        if (lane == (bi & 31)) v[bi >> 5] = -1e30f;
    }
}

// ====================================================================
// H[pair] = relu(A[i] + Bm[j] + b1) -> bf16
// ====================================================================
__global__ void build_h_bf16(const float* __restrict__ Av, const float* __restrict__ Bv,
                             const float* __restrict__ b1, const int* __restrict__ nbr,
                             __nv_bfloat16* __restrict__ H, int D) {
    int pair = blockIdx.x;
    int i = pair >> 3;
    int j = nbr[pair];
    const float* ar = Av + (size_t)i * D;
    const float* br = Bv + (size_t)j * D;
    __nv_bfloat16* hr = H + (size_t)pair * D;
    for (int k = threadIdx.x; k < D; k += blockDim.x)
        hr[k] = __float2bfloat16(fmaxf(ar[k] + br[k] + b1[k], 0.f));
}

// ====================================================================
// score[pair] = sigmoid(H2 . (w3[0]-w3[1]) + (b3[0]-b3[1]))
// ====================================================================
__global__ void score_kernel(const float* __restrict__ H2, const float* __restrict__ w3,
                             const float* __restrict__ b3, float* __restrict__ score,
                             int D, int stride) {
    int pair = blockIdx.x * (blockDim.x >> 5) + (threadIdx.x >> 5);
    int lane = threadIdx.x & 31;
    const float* h = H2 + (size_t)pair * stride;
    float s = 0.f;
    for (int k = lane; k < D; k += 32) s += h[k] * (w3[k] - w3[D + k]);
    #pragma unroll
    for (int o = 16; o; o >>= 1) s += __shfl_xor_sync(0xffffffffu, s, o);
    if (lane == 0) {
        s += b3[0] - b3[1];
        score[pair] = 1.f / (1.f + expf(-s));
    }
}

// ====================================================================
// softmax(logits), normalize weights, combine with bank
// ====================================================================
__global__ void combine(const float* __restrict__ logits, const int* __restrict__ idx,
                        const float* __restrict__ bank,
                        const float* __restrict__ sf, const float* __restrict__ sl,
                        const int* __restrict__ nbrf, const int* __restrict__ nbrl,
                        float* __restrict__ out) {
    __shared__ float p[B_][NC];
    __shared__ float colsum[NC];
    int i = threadIdx.x;
    const float* lr = logits + i * NC;
    float m = lr[0];
    #pragma unroll
    for (int c = 1; c < NC; c++) m = fmaxf(m, lr[c]);
    float e[NC]; float ssum = 0.f;
    #pragma unroll
    for (int c = 0; c < NC; c++) { e[c] = expf(lr[c] - m); ssum += e[c]; }
    float invs = 1.f / ssum;
    #pragma unroll
    for (int c = 0; c < NC; c++) p[i][c] = e[c] * invs;
    __syncthreads();
    if (i < NC) {
        float s = 0.f;
        for (int r = 0; r < B_; r++) s += p[r][i];
        colsum[i] = s;
    }
    __syncthreads();
    float Sf = 0.f, Sl = 0.f;
    #pragma unroll
    for (int t = 0; t < KNN; t++) { Sf += sf[i * KNN + t]; Sl += sl[i * KNN + t]; }
    float df = 1.f / (Sf + EPSV), dl = 1.f / (Sl + EPSV);
    float tf[NC], tl[NC];
    #pragma unroll
    for (int c = 0; c < NC; c++) { tf[c] = 0.f; tl[c] = 0.f; }
    #pragma unroll
    for (int t = 0; t < KNN; t++) {
        int jf = nbrf[i * KNN + t]; float wf = sf[i * KNN + t] * df;
        int jl = nbrl[i * KNN + t]; float wl = sl[i * KNN + t] * dl;
        #pragma unroll
        for (int c = 0; c < NC; c++) {
            tf[c] += wf * p[jf][c];
            tl[c] += wl * p[jl][c];
        }
    }
    float ef = (EPSV / (float)B_) * df;
    float el = (EPSV / (float)B_) * dl;
    #pragma unroll
    for (int c = 0; c < NC; c++) {
        float tgt = 0.5f * (tf[c] + ef * colsum[c]) + 0.5f * (tl[c] + el * colsum[c]);
        out[i * NC + c] = bank[(size_t)idx[i] * NC + c] * 0.9f + tgt * 0.1f;
    }
}

// ====================================================================
// launcher
// ====================================================================
extern "C" void kernel_launch(void* const* d_in, const int* in_sizes, int n_in,
                              void* d_out, int out_size) {
    const float* fer_x  = (const float*)d_in[0];
    const float* lm_x   = (const float*)d_in[1];
    const float* logits = (const float*)d_in[2];
    const int*   idx    = (const int*)  d_in[3];
    const float* bank   = (const float*)d_in[4];
    const float* f_win  = (const float*)d_in[5];
    const float* f_bin  = (const float*)d_in[6];
    const float* f_w1   = (const float*)d_in[7];
    const float* f_b1   = (const float*)d_in[8];
    const float* f_w2   = (const float*)d_in[9];
    const float* f_b2   = (const float*)d_in[10];
    const float* f_w3   = (const float*)d_in[11];
    const float* f_b3   = (const float*)d_in[12];
    const float* l_win  = (const float*)d_in[13];
    const float* l_bin  = (const float*)d_in[14];
    const float* l_w1   = (const float*)d_in[15];
    const float* l_b1   = (const float*)d_in[16];
    const float* l_w2   = (const float*)d_in[17];
    const float* l_b2   = (const float*)d_in[18];
    const float* l_w3   = (const float*)d_in[19];
    const float* l_b3   = (const float*)d_in[20];
    float* out = (float*)d_out;

    Scratch* s = nullptr;
    cudaGetSymbolAddress((void**)&s, g_s);
    cudaFuncSetAttribute(gemm_mma, cudaFuncAttributeMaxDynamicSharedMemorySize, MM_SMEM);

    convert_all<<<1024, 256>>>(f_win, f_w1, f_w2, fer_x, l_win, l_w1, lm_x, s);
    prep_lm<<<64, 256>>>(l_w2, l_b2, s);

    // --- discrete path: split-bf16 Gram matrices + top-8 ---
    gemm_mma<<<dim3(2, 2), 256, MM_SMEM>>>(
        s->xhi_fer, FERD, s->xhi_fer, FERD, nullptr, 0, s->G_fer, nullptr, B_, FERD);
    gemm_mma<<<dim3(2, 2), 256, MM_SMEM>>>(
        s->xhi_fer, FERD, s->xlo_fer, FERD, nullptr, 0, s->P_fer, nullptr, B_, FERD);
    gemm_mma<<<dim3(2, 2), 256, MM_SMEM>>>(
        s->xhi_lm, LMD, s->xhi_lm, LMD, nullptr, 0, s->G_lm, nullptr, B_, LMD);
    gemm_mma<<<dim3(2, 2), 256, MM_SMEM>>>(
        s->xhi_lm, LMD, s->xlo_lm, LMD, nullptr, 0, s->P_lm, nullptr, B_, LMD);
    topk8_warp<<<32, 256>>>(s->G_fer, s->P_fer, s->nbr_fer);
    topk8_warp<<<32, 256>>>(s->G_lm,  s->P_lm,  s->nbr_lm);

    // --- FER branch ---
    gemm_mma<<<dim3(FERD/128, B_/128), 256, MM_SMEM>>>(
        s->xhi_fer, FERD, s->w_in_b, FERD, f_bin, 0, nullptr, s->feats_fer_b, FERD, FERD);
    gemm_mma<<<dim3(1024/128, B_/128), 256, MM_SMEM>>>(
        s->feats_fer_b, FERD, s->w1_b, FERD, nullptr, 0, s->A_fer, nullptr, 1024, 1024);
    gemm_mma<<<dim3(1024/128, B_/128), 256, MM_SMEM>>>(
        s->feats_fer_b + 1024, FERD, s->w1_b + 1024, FERD, nullptr, 0, s->Bm_fer, nullptr, 1024, 1024);
    build_h_bf16<<<NPAIR, 256>>>(s->A_fer, s->Bm_fer, f_b1, s->nbr_fer, s->H_fer_b, 1024);
    gemm_mma<<<dim3(512/128, NPAIR/128), 256, MM_SMEM>>>(
        s->H_fer_b, 1024, s->w2_b, 1024, f_b2, 1, s->H2_fer, nullptr, 512, 1024);
    score_kernel<<<NPAIR/8, 256>>>(s->H2_fer, f_w3, f_b3, s->score_fer, 512, 512);

    // --- LM branch ---
    gemm_mma<<<dim3(LMD/128, B_/128), 256, MM_SMEM>>>(
        s->xhi_lm, LMD, s->l_win_b, LMD, l_bin, 0, nullptr, s->feats_lm_b, LMD, LMD);
    gemm_mma<<<dim3(1, B_/128), 256, MM_SMEM>>>(
        s->feats_lm_b, LMD, s->l_w1_b, LMD, nullptr, 0, s->A_lm, nullptr, 128, 128);
    gemm_mma<<<dim3(1, B_/128), 256, MM_SMEM>>>(
        s->feats_lm_b + 128, LMD, s->l_w1_b + 128, LMD, nullptr, 0, s->Bm_lm, nullptr, 128, 128);
    build_h_bf16<<<NPAIR, 128>>>(s->A_lm, s->Bm_lm, l_b1, s->nbr_lm, s->H_lm_b, 128);
    gemm_mma<<<dim3(1, NPAIR/128), 256, MM_SMEM>>>(
        s->H_lm_b, 128, s->l_w2_pad_b, 128, s->l_b2_pad, 1, s->H2_lm, nullptr, 128, 128);
    score_kernel<<<NPAIR/8, 256>>>(s->H2_lm, l_w3, l_b3, s->score_lm, 64, 128);

    // --- final combine ---
    combine<<<1, B_>>>(logits, idx, bank, s->score_fer, s->score_lm,
                       s->nbr_fer, s->nbr_lm, out);
}

// round 6
// speedup vs baseline: 2.2992x; 2.2992x over previous
#include <cuda_runtime.h>
#include <cuda_bf16.h>
#include <cstdint>
#include <math.h>

#define B_      256
#define FERD    2048
#define LMD     256
#define NC      7
#define KNN     8
#define NPAIR   (B_*KNN)     // 2048
#define EPSV    1e-8f

__device__ __forceinline__ uint32_t smem_to_u32(const void* p) {
    uint32_t a;
    asm("{ .reg .u64 t; cvta.to.shared.u64 t, %1; cvt.u32.u64 %0, t; }" : "=r"(a) : "l"(p));
    return a;
}

// ====================================================================
// scratch (no allocations allowed)
// ====================================================================
struct __align__(16) Scratch {
    // bf16 operands
    __nv_bfloat16 w_in_b[FERD*FERD];
    __nv_bfloat16 w1_b  [1024*FERD];
    __nv_bfloat16 w2_b  [512*1024];
    __nv_bfloat16 xhi_fer[B_*FERD];
    __nv_bfloat16 xlo_fer[B_*FERD];
    __nv_bfloat16 l_win_b[LMD*LMD];
    __nv_bfloat16 l_w1_b [128*LMD];
    __nv_bfloat16 xhi_lm [B_*LMD];
    __nv_bfloat16 xlo_lm [B_*LMD];
    __nv_bfloat16 feats_fer_b[B_*FERD];
    __nv_bfloat16 feats_lm_b [B_*LMD];
    __nv_bfloat16 H_fer_b[NPAIR*1024];
    __nv_bfloat16 H_lm_b [NPAIR*128];
    __nv_bfloat16 l_w2_pad_b[128*128];
    float         l_b2_pad[128];
    // fp32
    float G_fer[B_*B_], P_fer[B_*B_];
    float G_lm [B_*B_], P_lm [B_*B_];
    float A_fer[B_*1024], Bm_fer[B_*1024];
    float A_lm [B_*128],  Bm_lm [B_*128];
    float H2_fer[NPAIR*512];
    float H2_lm [NPAIR*128];
    float score_fer[NPAIR], score_lm[NPAIR];
    int   nbr_fer[NPAIR], nbr_lm[NPAIR];
    // split-K partial buffer (max 2M floats)
    float Cpart[2*1024*1024];
};
__device__ Scratch g_s;

// ====================================================================
// fp32 -> bf16 conversion of all tensor operands (hi/lo split for x)
// ====================================================================
#define CN1 (FERD*FERD)
#define CN2 (1024*FERD)
#define CN3 (512*1024)
#define CN4 (B_*FERD)
#define CN5 (LMD*LMD)
#define CN6 (128*LMD)
#define CN7 (B_*LMD)
#define CTOT (CN1+CN2+CN3+CN4+CN5+CN6+CN7)
__global__ void convert_all(const float* __restrict__ fw_in, const float* __restrict__ fw1,
                            const float* __restrict__ fw2,  const float* __restrict__ fx,
                            const float* __restrict__ lwin, const float* __restrict__ lw1,
                            const float* __restrict__ lx,   Scratch* s) {
    int total4 = CTOT / 4;
    for (int i = blockIdx.x * blockDim.x + threadIdx.x; i < total4;
         i += gridDim.x * blockDim.x) {
        int j = i * 4;
        const float* src; __nv_bfloat16* dst; __nv_bfloat16* lo = nullptr; int off;
        if      (j < CN1)                     { src=fw_in; dst=s->w_in_b;  off=j; }
        else if (j < CN1+CN2)                 { src=fw1;   dst=s->w1_b;    off=j-CN1; }
        else if (j < CN1+CN2+CN3)             { src=fw2;   dst=s->w2_b;    off=j-CN1-CN2; }
        else if (j < CN1+CN2+CN3+CN4)         { src=fx;    dst=s->xhi_fer; lo=s->xlo_fer;
                                                off=j-CN1-CN2-CN3; }
        else if (j < CN1+CN2+CN3+CN4+CN5)     { src=lwin;  dst=s->l_win_b; off=j-CN1-CN2-CN3-CN4; }
        else if (j < CN1+CN2+CN3+CN4+CN5+CN6) { src=lw1;   dst=s->l_w1_b;  off=j-CN1-CN2-CN3-CN4-CN5; }
        else                                  { src=lx;    dst=s->xhi_lm;  lo=s->xlo_lm;
                                                off=j-CN1-CN2-CN3-CN4-CN5-CN6; }
        float4 v = *(const float4*)(src + off);
        __nv_bfloat16 h0 = __float2bfloat16(v.x), h1 = __float2bfloat16(v.y);
        __nv_bfloat16 h2 = __float2bfloat16(v.z), h3 = __float2bfloat16(v.w);
        *(__nv_bfloat162*)(dst + off)     = __nv_bfloat162(h0, h1);
        *(__nv_bfloat162*)(dst + off + 2) = __nv_bfloat162(h2, h3);
        if (lo) {
            *(__nv_bfloat162*)(lo + off) = __nv_bfloat162(
                __float2bfloat16(v.x - __bfloat162float(h0)),
                __float2bfloat16(v.y - __bfloat162float(h1)));
            *(__nv_bfloat162*)(lo + off + 2) = __nv_bfloat162(
                __float2bfloat16(v.z - __bfloat162float(h2)),
                __float2bfloat16(v.w - __bfloat162float(h3)));
        }
    }
}

// pad LM w2 (64x128) to 128x128 bf16, pad b2 to 128 with zeros
__global__ void prep_lm(const float* __restrict__ w2, const float* __restrict__ b2,
                        Scratch* s) {
    int t = blockIdx.x * blockDim.x + threadIdx.x;
    if (t < 128 * 128) {
        int r = t >> 7, c = t & 127;
        s->l_w2_pad_b[t] = __float2bfloat16(r < 64 ? w2[r * 128 + c] : 0.f);
    }
    if (t < 128) s->l_b2_pad[t] = (t < 64) ? b2[t] : 0.f;
}

// ====================================================================
// bf16 HMMA GEMM with job-fusion (grid.z) and split-K partial output.
// C[M,N] = A(job)(MxK) . B(job)(NxK)^T ; block tile 128x128, BK=64,
// 8 warps, mma m16n8k16, 3-stage cp.async pipeline.
// z = split*njobs + job. If Cpart != null: write fp32 partial at
// Cpart[z*M*N] (no bias/relu). Else direct output with bias/relu:
// bf16 via Cb0 (njobs==1) or fp32 via Cf0/Cf1 per job.
// ====================================================================
#define MM_LDS   72
#define MM_ATILE (128*MM_LDS*2)
#define MM_BUF   (2*MM_ATILE)
#define MM_SMEM  (3*MM_BUF)          // 3-stage: 110592 bytes

__global__ void __launch_bounds__(256)
gemm_mma(const __nv_bfloat16* __restrict__ A0, const __nv_bfloat16* __restrict__ A1, int lda,
         const __nv_bfloat16* __restrict__ B0, const __nv_bfloat16* __restrict__ B1, int ldb,
         const float* __restrict__ bias, int relu,
         float* __restrict__ Cf0, float* __restrict__ Cf1,
         __nv_bfloat16* __restrict__ Cb0,
         float* __restrict__ Cpart,
         int njobs, int N, int K)
{
    extern __shared__ char smem[];
    uint32_t sb = smem_to_u32(smem);
    int tid = threadIdx.x;
    int lane = tid & 31, warp = tid >> 5;
    int wm = warp >> 2, wn = warp & 3;
    int m0 = blockIdx.y * 128, n0 = blockIdx.x * 128;

    int z = blockIdx.z;
    int job   = (njobs == 2) ? (z & 1) : 0;
    int split = (njobs == 2) ? (z >> 1) : z;
    int nsplit = gridDim.z / njobs;
    int Ksplit = K / nsplit;
    int kbase = split * Ksplit;
    int nk = Ksplit >> 6;

    const __nv_bfloat16* A = job ? A1 : A0;
    const __nv_bfloat16* B = job ? B1 : B0;

    float acc[4][4][4];
    #pragma unroll
    for (int i = 0; i < 4; i++)
        #pragma unroll
        for (int j = 0; j < 4; j++)
            #pragma unroll
            for (int q = 0; q < 4; q++) acc[i][j][q] = 0.f;

    auto issue = [&](int kt) {
        int st = kt % 3;
        uint32_t base = sb + st * MM_BUF;
        int k0 = kbase + kt * 64;
        #pragma unroll
        for (int u = 0; u < 4; u++) {
            int cc = tid * 4 + u;
            int row = cc >> 3;
            int col = (cc & 7) * 8;
            uint32_t da = base + (uint32_t)(row * MM_LDS + col) * 2;
            const __nv_bfloat16* ga = A + (size_t)(m0 + row) * lda + k0 + col;
            asm volatile("cp.async.cg.shared.global [%0], [%1], 16;" :: "r"(da), "l"(ga));
            const __nv_bfloat16* gb = B + (size_t)(n0 + row) * ldb + k0 + col;
            asm volatile("cp.async.cg.shared.global [%0], [%1], 16;"
                         :: "r"(da + MM_ATILE), "l"(gb));
        }
        asm volatile("cp.async.commit_group;" ::: "memory");
    };

    issue(0);
    if (nk > 1) issue(1);
    for (int kt = 0; kt < nk; kt++) {
        if (kt + 2 < nk) {
            issue(kt + 2);
            asm volatile("cp.async.wait_group 2;" ::: "memory");
        } else if (kt + 1 < nk) {
            asm volatile("cp.async.wait_group 1;" ::: "memory");
        } else {
            asm volatile("cp.async.wait_group 0;" ::: "memory");
        }
        __syncthreads();

        uint32_t aBase = sb + (kt % 3) * MM_BUF;
        uint32_t bBase = aBase + MM_ATILE;
        #pragma unroll
        for (int ks = 0; ks < 4; ks++) {
            int k = ks * 16;
            uint32_t af[4][4];
            #pragma unroll
            for (int im = 0; im < 4; im++) {
                int row = wm * 64 + im * 16 + (lane & 15);
                int kg = (lane >> 4) * 8;
                uint32_t addr = aBase + (uint32_t)(row * MM_LDS + k + kg) * 2;
                asm volatile("ldmatrix.sync.aligned.m8n8.x4.shared.b16 {%0,%1,%2,%3}, [%4];"
                             : "=r"(af[im][0]), "=r"(af[im][1]),
                               "=r"(af[im][2]), "=r"(af[im][3])
                             : "r"(addr));
            }
            uint32_t bf[4][2];
            #pragma unroll
            for (int in = 0; in < 4; in++) {
                int l = lane & 15;
                int n = wn * 32 + in * 8 + (l & 7);
                int kg = (l >> 3) * 8;
                uint32_t addr = bBase + (uint32_t)(n * MM_LDS + k + kg) * 2;
                asm volatile("ldmatrix.sync.aligned.m8n8.x2.shared.b16 {%0,%1}, [%2];"
                             : "=r"(bf[in][0]), "=r"(bf[in][1])
                             : "r"(addr));
            }
            #pragma unroll
            for (int im = 0; im < 4; im++)
                #pragma unroll
                for (int in = 0; in < 4; in++) {
                    asm volatile(
                        "mma.sync.aligned.m16n8k16.row.col.f32.bf16.bf16.f32 "
                        "{%0,%1,%2,%3}, {%4,%5,%6,%7}, {%8,%9}, {%0,%1,%2,%3};"
                        : "+f"(acc[im][in][0]), "+f"(acc[im][in][1]),
                          "+f"(acc[im][in][2]), "+f"(acc[im][in][3])
                        : "r"(af[im][0]), "r"(af[im][1]), "r"(af[im][2]), "r"(af[im][3]),
                          "r"(bf[in][0]), "r"(bf[in][1]));
                }
        }
        __syncthreads();
    }

    // -------- epilogue --------
    if (Cpart) {
        size_t MN = (size_t)gridDim.y * 128 * N;
        float* cp = Cpart + (size_t)z * MN;
        #pragma unroll
        for (int im = 0; im < 4; im++) {
            int m = m0 + wm * 64 + im * 16 + (lane >> 2);
            #pragma unroll
            for (int in = 0; in < 4; in++) {
                int n = n0 + wn * 32 + in * 8 + (lane & 3) * 2;
                *(float2*)(cp + (size_t)m * N + n) =
                    make_float2(acc[im][in][0], acc[im][in][1]);
                *(float2*)(cp + (size_t)(m + 8) * N + n) =
                    make_float2(acc[im][in][2], acc[im][in][3]);
            }
        }
        return;
    }
    float* Cf = job ? Cf1 : Cf0;
    #pragma unroll
    for (int im = 0; im < 4; im++) {
        int m = m0 + wm * 64 + im * 16 + (lane >> 2);
        #pragma unroll
        for (int in = 0; in < 4; in++) {
            int n = n0 + wn * 32 + in * 8 + (lane & 3) * 2;
            float b0 = bias ? bias[n]     : 0.f;
            float b1 = bias ? bias[n + 1] : 0.f;
            float v00 = acc[im][in][0] + b0, v01 = acc[im][in][1] + b1;
            float v10 = acc[im][in][2] + b0, v11 = acc[im][in][3] + b1;
            if (relu) {
                v00 = fmaxf(v00, 0.f); v01 = fmaxf(v01, 0.f);
                v10 = fmaxf(v10, 0.f); v11 = fmaxf(v11, 0.f);
            }
            if (Cb0) {
                *(__nv_bfloat162*)(Cb0 + (size_t)m * N + n) =
                    __floats2bfloat162_rn(v00, v01);
                *(__nv_bfloat162*)(Cb0 + (size_t)(m + 8) * N + n) =
                    __floats2bfloat162_rn(v10, v11);
            } else {
                *(float2*)(Cf + (size_t)m * N + n)       = make_float2(v00, v01);
                *(float2*)(Cf + (size_t)(m + 8) * N + n) = make_float2(v10, v11);
            }
        }
    }
}

// ====================================================================
// split-K reduce: sum nsplit partials per job, add bias/relu, emit
// fp32 (of0/of1 per job) or bf16 (ob0, job 0 only).
// ====================================================================
__global__ void reduce_parts(const float* __restrict__ part, int nsplit, int njobs,
                             long MN, int N,
                             const float* __restrict__ bias0,
                             const float* __restrict__ bias1, int relu,
                             float* __restrict__ of0, float* __restrict__ of1,
                             __nv_bfloat16* __restrict__ ob0) {
    long MN4 = MN >> 2;
    long total = (long)njobs * MN4;
    for (long idx = blockIdx.x * (long)blockDim.x + threadIdx.x; idx < total;
         idx += (long)gridDim.x * blockDim.x) {
        int  job = (int)(idx / MN4);
        long e4  = idx - (long)job * MN4;
        float4 s = make_float4(0.f, 0.f, 0.f, 0.f);
        #pragma unroll 1
        for (int sp = 0; sp < nsplit; sp++) {
            const float4* p = (const float4*)(part + ((size_t)(sp * njobs + job)) * MN) + e4;
            float4 v = *p;
            s.x += v.x; s.y += v.y; s.z += v.z; s.w += v.w;
        }
        const float* bias = job ? bias1 : bias0;
        if (bias) {
            int col = (int)((e4 * 4) % N);
            s.x += bias[col]; s.y += bias[col + 1]; s.z += bias[col + 2]; s.w += bias[col + 3];
        }
        if (relu) {
            s.x = fmaxf(s.x, 0.f); s.y = fmaxf(s.y, 0.f);
            s.z = fmaxf(s.z, 0.f); s.w = fmaxf(s.w, 0.f);
        }
        if (job == 0 && ob0) {
            *(__nv_bfloat162*)(ob0 + e4 * 4)     = __floats2bfloat162_rn(s.x, s.y);
            *(__nv_bfloat162*)(ob0 + e4 * 4 + 2) = __floats2bfloat162_rn(s.z, s.w);
        } else {
            float* o = job ? of1 : of0;
            *((float4*)o + e4) = s;
        }
    }
}

// ====================================================================
// top-8 per row from split Gram matrices
// ====================================================================
__global__ void topk8_warp(const float* __restrict__ G, const float* __restrict__ P,
                           int* __restrict__ nbr) {
    int warp = blockIdx.x * (blockDim.x >> 5) + (threadIdx.x >> 5);
    int lane = threadIdx.x & 31;
    if (warp >= B_) return;
    float v[8];
    #pragma unroll
    for (int t = 0; t < 8; t++) {
        int j = lane + t * 32;
        if (j == warp) { v[t] = -1e30f; continue; }
        float g  = G[(size_t)warp * B_ + j];
        float p1 = P[(size_t)warp * B_ + j];
        float p2 = P[(size_t)j * B_ + warp];
        float dg = G[(size_t)j * B_ + j];
        float dp = P[(size_t)j * B_ + j];
        v[t] = (g + p1 + p2) * rsqrtf(dg + 2.f * dp);
    }
    for (int t = 0; t < KNN; t++) {
        float bv = -1e30f; int bi = 0x7fffffff;
        #pragma unroll
        for (int q = 0; q < 8; q++) {
            int j = lane + q * 32;
            if (v[q] > bv || (v[q] == bv && j < bi)) { bv = v[q]; bi = j; }
        }
        #pragma unroll
        for (int o = 16; o; o >>= 1) {
            float ov = __shfl_xor_sync(0xffffffffu, bv, o);
            int   oi = __shfl_xor_sync(0xffffffffu, bi, o);
            if (ov > bv || (ov == bv && oi < bi)) { bv = ov; bi = oi; }
        }
        if (lane == 0) nbr[warp * KNN + t] = bi;
        if (lane == (bi & 31)) v[bi >> 5] = -1e30f;
    }
}

// ====================================================================
// H[pair] = relu(A[i] + Bm[j] + b1) -> bf16
// ====================================================================
__global__ void build_h_bf16(const float* __restrict__ Av, const float* __restrict__ Bv,
                             const float* __restrict__ b1, const int* __restrict__ nbr,
                             __nv_bfloat16* __restrict__ H, int D) {
    int pair = blockIdx.x;
    int i = pair >> 3;
    int j = nbr[pair];
    const float* ar = Av + (size_t)i * D;
    const float* br = Bv + (size_t)j * D;
    __nv_bfloat16* hr = H + (size_t)pair * D;
    for (int k = threadIdx.x; k < D; k += blockDim.x)
        hr[k] = __float2bfloat16(fmaxf(ar[k] + br[k] + b1[k], 0.f));
}

// ====================================================================
// score[pair] = sigmoid(H2 . (w3[0]-w3[1]) + (b3[0]-b3[1]))
// ====================================================================
__global__ void score_kernel(const float* __restrict__ H2, const float* __restrict__ w3,
                             const float* __restrict__ b3, float* __restrict__ score,
                             int D, int stride) {
    int pair = blockIdx.x * (blockDim.x >> 5) + (threadIdx.x >> 5);
    int lane = threadIdx.x & 31;
    const float* h = H2 + (size_t)pair * stride;
    float s = 0.f;
    for (int k = lane; k < D; k += 32) s += h[k] * (w3[k] - w3[D + k]);
    #pragma unroll
    for (int o = 16; o; o >>= 1) s += __shfl_xor_sync(0xffffffffu, s, o);
    if (lane == 0) {
        s += b3[0] - b3[1];
        score[pair] = 1.f / (1.f + expf(-s));
    }
}

// ====================================================================
// softmax(logits), normalize weights, combine with bank
// ====================================================================
__global__ void combine(const float* __restrict__ logits, const int* __restrict__ idx,
                        const float* __restrict__ bank,
                        const float* __restrict__ sf, const float* __restrict__ sl,
                        const int* __restrict__ nbrf, const int* __restrict__ nbrl,
                        float* __restrict__ out) {
    __shared__ float p[B_][NC];
    __shared__ float colsum[NC];
    int i = threadIdx.x;
    const float* lr = logits + i * NC;
    float m = lr[0];
    #pragma unroll
    for (int c = 1; c < NC; c++) m = fmaxf(m, lr[c]);
    float e[NC]; float ssum = 0.f;
    #pragma unroll
    for (int c = 0; c < NC; c++) { e[c] = expf(lr[c] - m); ssum += e[c]; }
    float invs = 1.f / ssum;
    #pragma unroll
    for (int c = 0; c < NC; c++) p[i][c] = e[c] * invs;
    __syncthreads();
    if (i < NC) {
        float s = 0.f;
        for (int r = 0; r < B_; r++) s += p[r][i];
        colsum[i] = s;
    }
    __syncthreads();
    float Sf = 0.f, Sl = 0.f;
    #pragma unroll
    for (int t = 0; t < KNN; t++) { Sf += sf[i * KNN + t]; Sl += sl[i * KNN + t]; }
    float df = 1.f / (Sf + EPSV), dl = 1.f / (Sl + EPSV);
    float tf[NC], tl[NC];
    #pragma unroll
    for (int c = 0; c < NC; c++) { tf[c] = 0.f; tl[c] = 0.f; }
    #pragma unroll
    for (int t = 0; t < KNN; t++) {
        int jf = nbrf[i * KNN + t]; float wf = sf[i * KNN + t] * df;
        int jl = nbrl[i * KNN + t]; float wl = sl[i * KNN + t] * dl;
        #pragma unroll
        for (int c = 0; c < NC; c++) {
            tf[c] += wf * p[jf][c];
            tl[c] += wl * p[jl][c];
        }
    }
    float ef = (EPSV / (float)B_) * df;
    float el = (EPSV / (float)B_) * dl;
    #pragma unroll
    for (int c = 0; c < NC; c++) {
        float tgt = 0.5f * (tf[c] + ef * colsum[c]) + 0.5f * (tl[c] + el * colsum[c]);
        out[i * NC + c] = bank[(size_t)idx[i] * NC + c] * 0.9f + tgt * 0.1f;
    }
}

// ====================================================================
// launcher
// ====================================================================
extern "C" void kernel_launch(void* const* d_in, const int* in_sizes, int n_in,
                              void* d_out, int out_size) {
    const float* fer_x  = (const float*)d_in[0];
    const float* lm_x   = (const float*)d_in[1];
    const float* logits = (const float*)d_in[2];
    const int*   idx    = (const int*)  d_in[3];
    const float* bank   = (const float*)d_in[4];
    const float* f_win  = (const float*)d_in[5];
    const float* f_bin  = (const float*)d_in[6];
    const float* f_w1   = (const float*)d_in[7];
    const float* f_b1   = (const float*)d_in[8];
    const float* f_w2   = (const float*)d_in[9];
    const float* f_b2   = (const float*)d_in[10];
    const float* f_w3   = (const float*)d_in[11];
    const float* f_b3   = (const float*)d_in[12];
    const float* l_win  = (const float*)d_in[13];
    const float* l_bin  = (const float*)d_in[14];
    const float* l_w1   = (const float*)d_in[15];
    const float* l_b1   = (const float*)d_in[16];
    const float* l_w2   = (const float*)d_in[17];
    const float* l_b2   = (const float*)d_in[18];
    const float* l_w3   = (const float*)d_in[19];
    const float* l_b3   = (const float*)d_in[20];
    float* out = (float*)d_out;

    Scratch* s = nullptr;
    cudaGetSymbolAddress((void**)&s, g_s);
    if (!s) return;
    cudaFuncSetAttribute(gemm_mma, cudaFuncAttributeMaxDynamicSharedMemorySize, MM_SMEM);

    convert_all<<<1024, 256>>>(f_win, f_w1, f_w2, fer_x, l_win, l_w1, lm_x, s);
    prep_lm<<<64, 256>>>(l_w2, l_b2, s);

    // --- discrete path: split-bf16 Gram matrices + top-8 ---
    // FER sim: jobs {G: xhi.xhi^T, P: xhi.xlo^T}, split-K 8 -> grid.z = 16
    gemm_mma<<<dim3(2, 2, 16), 256, MM_SMEM>>>(
        s->xhi_fer, s->xhi_fer, FERD, s->xhi_fer, s->xlo_fer, FERD,
        nullptr, 0, nullptr, nullptr, nullptr, s->Cpart, 2, B_, FERD);
    reduce_parts<<<128, 256>>>(s->Cpart, 8, 2, (long)B_ * B_, B_,
                               nullptr, nullptr, 0, s->G_fer, s->P_fer, nullptr);
    topk8_warp<<<32, 256>>>(s->G_fer, s->P_fer, s->nbr_fer);
    // LM sim: direct, jobs fused, no split
    gemm_mma<<<dim3(2, 2, 2), 256, MM_SMEM>>>(
        s->xhi_lm, s->xhi_lm, LMD, s->xhi_lm, s->xlo_lm, LMD,
        nullptr, 0, s->G_lm, s->P_lm, nullptr, nullptr, 2, B_, LMD);
    topk8_warp<<<32, 256>>>(s->G_lm, s->P_lm, s->nbr_lm);

    // --- FER branch ---
    // feats = x @ w_in^T + b_in (split-K 4 -> reduce to bf16)
    gemm_mma<<<dim3(FERD/128, B_/128, 4), 256, MM_SMEM>>>(
        s->xhi_fer, nullptr, FERD, s->w_in_b, nullptr, FERD,
        nullptr, 0, nullptr, nullptr, nullptr, s->Cpart, 1, FERD, FERD);
    reduce_parts<<<256, 256>>>(s->Cpart, 4, 1, (long)B_ * FERD, FERD,
                               f_bin, nullptr, 0, nullptr, nullptr, s->feats_fer_b);
    // A = f1 @ w1a^T ; Bm = f2 @ w1b^T (jobs fused, split-K 2)
    gemm_mma<<<dim3(1024/128, B_/128, 4), 256, MM_SMEM>>>(
        s->feats_fer_b, s->feats_fer_b + 1024, FERD, s->w1_b, s->w1_b + 1024, FERD,
        nullptr, 0, nullptr, nullptr, nullptr, s->Cpart, 2, 1024, 1024);
    reduce_parts<<<256, 256>>>(s->Cpart, 2, 2, (long)B_ * 1024, 1024,
                               nullptr, nullptr, 0, s->A_fer, s->Bm_fer, nullptr);
    build_h_bf16<<<NPAIR, 256>>>(s->A_fer, s->Bm_fer, f_b1, s->nbr_fer, s->H_fer_b, 1024);
    // H2 = relu(H @ w2^T + b2) (split-K 2)
    gemm_mma<<<dim3(512/128, NPAIR/128, 2), 256, MM_SMEM>>>(
        s->H_fer_b, nullptr, 1024, s->w2_b, nullptr, 1024,
        nullptr, 0, nullptr, nullptr, nullptr, s->Cpart, 1, 512, 1024);
    reduce_parts<<<256, 256>>>(s->Cpart, 2, 1, (long)NPAIR * 512, 512,
                               f_b2, nullptr, 1, s->H2_fer, nullptr, nullptr);
    score_kernel<<<NPAIR/8, 256>>>(s->H2_fer, f_w3, f_b3, s->score_fer, 512, 512);

    // --- LM branch (all direct, small) ---
    gemm_mma<<<dim3(LMD/128, B_/128, 1), 256, MM_SMEM>>>(
        s->xhi_lm, nullptr, LMD, s->l_win_b, nullptr, LMD,
        l_bin, 0, nullptr, nullptr, s->feats_lm_b, nullptr, 1, LMD, LMD);
    gemm_mma<<<dim3(1, B_/128, 2), 256, MM_SMEM>>>(
        s->feats_lm_b, s->feats_lm_b + 128, LMD, s->l_w1_b, s->l_w1_b + 128, LMD,
        nullptr, 0, s->A_lm, s->Bm_lm, nullptr, nullptr, 2, 128, 128);
    build_h_bf16<<<NPAIR, 128>>>(s->A_lm, s->Bm_lm, l_b1, s->nbr_lm, s->H_lm_b, 128);
    gemm_mma<<<dim3(1, NPAIR/128, 1), 256, MM_SMEM>>>(
        s->H_lm_b, nullptr, 128, s->l_w2_pad_b, nullptr, 128,
        s->l_b2_pad, 1, s->H2_lm, nullptr, nullptr, nullptr, 1, 128, 128);
    score_kernel<<<NPAIR/8, 256>>>(s->H2_lm, l_w3, l_b3, s->score_lm, 64, 128);

    // --- final combine ---
    combine<<<1, B_>>>(logits, idx, bank, s->score_fer, s->score_lm,
                       s->nbr_fer, s->nbr_lm, out);
}

// round 7
// speedup vs baseline: 2.7664x; 1.2032x over previous
#include <cuda_runtime.h>
#include <cuda_bf16.h>
#include <cstdint>
#include <math.h>

#define B_      256
#define FERD    2048
#define LMD     256
#define NC      7
#define KNN     8
#define NPAIR   (B_*KNN)     // 2048
#define EPSV    1e-8f

__device__ __forceinline__ uint32_t smem_to_u32(const void* p) {
    uint32_t a;
    asm("{ .reg .u64 t; cvta.to.shared.u64 t, %1; cvt.u32.u64 %0, t; }" : "=r"(a) : "l"(p));
    return a;
}

// ====================================================================
// scratch (no allocations allowed)
// ====================================================================
struct __align__(16) Scratch {
    // bf16 operands
    __nv_bfloat16 w_in_b[FERD*FERD];
    __nv_bfloat16 w1_b  [1024*FERD];
    __nv_bfloat16 w2_b  [512*1024];
    __nv_bfloat16 xhi_fer[B_*FERD];
    __nv_bfloat16 xlo_fer[B_*FERD];
    __nv_bfloat16 l_win_b[LMD*LMD];
    __nv_bfloat16 l_w1_b [128*LMD];
    __nv_bfloat16 xhi_lm [B_*LMD];
    __nv_bfloat16 xlo_lm [B_*LMD];
    __nv_bfloat16 feats_fer_b[B_*FERD];
    __nv_bfloat16 feats_lm_b [B_*LMD];
    __nv_bfloat16 H_fer_b[NPAIR*1024];
    __nv_bfloat16 H_lm_b [NPAIR*128];
    __nv_bfloat16 l_w2_pad_b[128*128];
    float         l_b2_pad[128];
    // fp32
    float G_fer[B_*B_], P_fer[B_*B_];
    float G_lm [B_*B_], P_lm [B_*B_];
    float A_lm [B_*128],  Bm_lm [B_*128];
    float H2_lm [NPAIR*128];
    float score_fer[NPAIR], score_lm[NPAIR];
    int   nbr_fer[NPAIR], nbr_lm[NPAIR];
    // split-K partial buffer (max 2M floats)
    float Cpart[2*1024*1024];
};
__device__ Scratch g_s;

// ====================================================================
// fp32 -> bf16 conversion of all tensor operands (hi/lo split for x)
// + LM w2/b2 padding (folded in)
// ====================================================================
#define CN1 (FERD*FERD)
#define CN2 (1024*FERD)
#define CN3 (512*1024)
#define CN4 (B_*FERD)
#define CN5 (LMD*LMD)
#define CN6 (128*LMD)
#define CN7 (B_*LMD)
#define CTOT (CN1+CN2+CN3+CN4+CN5+CN6+CN7)
__global__ void convert_all(const float* __restrict__ fw_in, const float* __restrict__ fw1,
                            const float* __restrict__ fw2,  const float* __restrict__ fx,
                            const float* __restrict__ lwin, const float* __restrict__ lw1,
                            const float* __restrict__ lx,
                            const float* __restrict__ lw2,  const float* __restrict__ lb2,
                            Scratch* s) {
    int total4 = CTOT / 4;
    for (int i = blockIdx.x * blockDim.x + threadIdx.x; i < total4;
         i += gridDim.x * blockDim.x) {
        int j = i * 4;
        const float* src; __nv_bfloat16* dst; __nv_bfloat16* lo = nullptr; int off;
        if      (j < CN1)                     { src=fw_in; dst=s->w_in_b;  off=j; }
        else if (j < CN1+CN2)                 { src=fw1;   dst=s->w1_b;    off=j-CN1; }
        else if (j < CN1+CN2+CN3)             { src=fw2;   dst=s->w2_b;    off=j-CN1-CN2; }
        else if (j < CN1+CN2+CN3+CN4)         { src=fx;    dst=s->xhi_fer; lo=s->xlo_fer;
                                                off=j-CN1-CN2-CN3; }
        else if (j < CN1+CN2+CN3+CN4+CN5)     { src=lwin;  dst=s->l_win_b; off=j-CN1-CN2-CN3-CN4; }
        else if (j < CN1+CN2+CN3+CN4+CN5+CN6) { src=lw1;   dst=s->l_w1_b;  off=j-CN1-CN2-CN3-CN4-CN5; }
        else                                  { src=lx;    dst=s->xhi_lm;  lo=s->xlo_lm;
                                                off=j-CN1-CN2-CN3-CN4-CN5-CN6; }
        float4 v = *(const float4*)(src + off);
        __nv_bfloat16 h0 = __float2bfloat16(v.x), h1 = __float2bfloat16(v.y);
        __nv_bfloat16 h2 = __float2bfloat16(v.z), h3 = __float2bfloat16(v.w);
        *(__nv_bfloat162*)(dst + off)     = __nv_bfloat162(h0, h1);
        *(__nv_bfloat162*)(dst + off + 2) = __nv_bfloat162(h2, h3);
        if (lo) {
            *(__nv_bfloat162*)(lo + off) = __nv_bfloat162(
                __float2bfloat16(v.x - __bfloat162float(h0)),
                __float2bfloat16(v.y - __bfloat162float(h1)));
            *(__nv_bfloat162*)(lo + off + 2) = __nv_bfloat162(
                __float2bfloat16(v.z - __bfloat162float(h2)),
                __float2bfloat16(v.w - __bfloat162float(h3)));
        }
    }
    // LM w2/b2 padding (tiny)
    int t = blockIdx.x * blockDim.x + threadIdx.x;
    if (t < 128 * 128) {
        int r = t >> 7, c = t & 127;
        s->l_w2_pad_b[t] = __float2bfloat16(r < 64 ? lw2[r * 128 + c] : 0.f);
    }
    if (t < 128) s->l_b2_pad[t] = (t < 64) ? lb2[t] : 0.f;
}

// ====================================================================
// bf16 HMMA GEMM with job-fusion (grid.z) and split-K partial output.
// (unchanged from round 6)
// ====================================================================
#define MM_LDS   72
#define MM_ATILE (128*MM_LDS*2)
#define MM_BUF   (2*MM_ATILE)
#define MM_SMEM  (3*MM_BUF)          // 110592 bytes

__global__ void __launch_bounds__(256)
gemm_mma(const __nv_bfloat16* __restrict__ A0, const __nv_bfloat16* __restrict__ A1, int lda,
         const __nv_bfloat16* __restrict__ B0, const __nv_bfloat16* __restrict__ B1, int ldb,
         const float* __restrict__ bias, int relu,
         float* __restrict__ Cf0, float* __restrict__ Cf1,
         __nv_bfloat16* __restrict__ Cb0,
         float* __restrict__ Cpart,
         int njobs, int N, int K)
{
    extern __shared__ char smem[];
    uint32_t sb = smem_to_u32(smem);
    int tid = threadIdx.x;
    int lane = tid & 31, warp = tid >> 5;
    int wm = warp >> 2, wn = warp & 3;
    int m0 = blockIdx.y * 128, n0 = blockIdx.x * 128;

    int z = blockIdx.z;
    int job   = (njobs == 2) ? (z & 1) : 0;
    int split = (njobs == 2) ? (z >> 1) : z;
    int nsplit = gridDim.z / njobs;
    int Ksplit = K / nsplit;
    int kbase = split * Ksplit;
    int nk = Ksplit >> 6;

    const __nv_bfloat16* A = job ? A1 : A0;
    const __nv_bfloat16* B = job ? B1 : B0;

    float acc[4][4][4];
    #pragma unroll
    for (int i = 0; i < 4; i++)
        #pragma unroll
        for (int j = 0; j < 4; j++)
            #pragma unroll
            for (int q = 0; q < 4; q++) acc[i][j][q] = 0.f;

    auto issue = [&](int kt) {
        int st = kt % 3;
        uint32_t base = sb + st * MM_BUF;
        int k0 = kbase + kt * 64;
        #pragma unroll
        for (int u = 0; u < 4; u++) {
            int cc = tid * 4 + u;
            int row = cc >> 3;
            int col = (cc & 7) * 8;
            uint32_t da = base + (uint32_t)(row * MM_LDS + col) * 2;
            const __nv_bfloat16* ga = A + (size_t)(m0 + row) * lda + k0 + col;
            asm volatile("cp.async.cg.shared.global [%0], [%1], 16;" :: "r"(da), "l"(ga));
            const __nv_bfloat16* gb = B + (size_t)(n0 + row) * ldb + k0 + col;
            asm volatile("cp.async.cg.shared.global [%0], [%1], 16;"
                         :: "r"(da + MM_ATILE), "l"(gb));
        }
        asm volatile("cp.async.commit_group;" ::: "memory");
    };

    issue(0);
    if (nk > 1) issue(1);
    for (int kt = 0; kt < nk; kt++) {
        if (kt + 2 < nk) {
            issue(kt + 2);
            asm volatile("cp.async.wait_group 2;" ::: "memory");
        } else if (kt + 1 < nk) {
            asm volatile("cp.async.wait_group 1;" ::: "memory");
        } else {
            asm volatile("cp.async.wait_group 0;" ::: "memory");
        }
        __syncthreads();

        uint32_t aBase = sb + (kt % 3) * MM_BUF;
        uint32_t bBase = aBase + MM_ATILE;
        #pragma unroll
        for (int ks = 0; ks < 4; ks++) {
            int k = ks * 16;
            uint32_t af[4][4];
            #pragma unroll
            for (int im = 0; im < 4; im++) {
                int row = wm * 64 + im * 16 + (lane & 15);
                int kg = (lane >> 4) * 8;
                uint32_t addr = aBase + (uint32_t)(row * MM_LDS + k + kg) * 2;
                asm volatile("ldmatrix.sync.aligned.m8n8.x4.shared.b16 {%0,%1,%2,%3}, [%4];"
                             : "=r"(af[im][0]), "=r"(af[im][1]),
                               "=r"(af[im][2]), "=r"(af[im][3])
                             : "r"(addr));
            }
            uint32_t bf[4][2];
            #pragma unroll
            for (int in = 0; in < 4; in++) {
                int l = lane & 15;
                int n = wn * 32 + in * 8 + (l & 7);
                int kg = (l >> 3) * 8;
                uint32_t addr = bBase + (uint32_t)(n * MM_LDS + k + kg) * 2;
                asm volatile("ldmatrix.sync.aligned.m8n8.x2.shared.b16 {%0,%1}, [%2];"
                             : "=r"(bf[in][0]), "=r"(bf[in][1])
                             : "r"(addr));
            }
            #pragma unroll
            for (int im = 0; im < 4; im++)
                #pragma unroll
                for (int in = 0; in < 4; in++) {
                    asm volatile(
                        "mma.sync.aligned.m16n8k16.row.col.f32.bf16.bf16.f32 "
                        "{%0,%1,%2,%3}, {%4,%5,%6,%7}, {%8,%9}, {%0,%1,%2,%3};"
                        : "+f"(acc[im][in][0]), "+f"(acc[im][in][1]),
                          "+f"(acc[im][in][2]), "+f"(acc[im][in][3])
                        : "r"(af[im][0]), "r"(af[im][1]), "r"(af[im][2]), "r"(af[im][3]),
                          "r"(bf[in][0]), "r"(bf[in][1]));
                }
        }
        __syncthreads();
    }

    if (Cpart) {
        size_t MN = (size_t)gridDim.y * 128 * N;
        float* cp = Cpart + (size_t)z * MN;
        #pragma unroll
        for (int im = 0; im < 4; im++) {
            int m = m0 + wm * 64 + im * 16 + (lane >> 2);
            #pragma unroll
            for (int in = 0; in < 4; in++) {
                int n = n0 + wn * 32 + in * 8 + (lane & 3) * 2;
                *(float2*)(cp + (size_t)m * N + n) =
                    make_float2(acc[im][in][0], acc[im][in][1]);
                *(float2*)(cp + (size_t)(m + 8) * N + n) =
                    make_float2(acc[im][in][2], acc[im][in][3]);
            }
        }
        return;
    }
    float* Cf = job ? Cf1 : Cf0;
    #pragma unroll
    for (int im = 0; im < 4; im++) {
        int m = m0 + wm * 64 + im * 16 + (lane >> 2);
        #pragma unroll
        for (int in = 0; in < 4; in++) {
            int n = n0 + wn * 32 + in * 8 + (lane & 3) * 2;
            float b0 = bias ? bias[n]     : 0.f;
            float b1 = bias ? bias[n + 1] : 0.f;
            float v00 = acc[im][in][0] + b0, v01 = acc[im][in][1] + b1;
            float v10 = acc[im][in][2] + b0, v11 = acc[im][in][3] + b1;
            if (relu) {
                v00 = fmaxf(v00, 0.f); v01 = fmaxf(v01, 0.f);
                v10 = fmaxf(v10, 0.f); v11 = fmaxf(v11, 0.f);
            }
            if (Cb0) {
                *(__nv_bfloat162*)(Cb0 + (size_t)m * N + n) =
                    __floats2bfloat162_rn(v00, v01);
                *(__nv_bfloat162*)(Cb0 + (size_t)(m + 8) * N + n) =
                    __floats2bfloat162_rn(v10, v11);
            } else {
                *(float2*)(Cf + (size_t)m * N + n)       = make_float2(v00, v01);
                *(float2*)(Cf + (size_t)(m + 8) * N + n) = make_float2(v10, v11);
            }
        }
    }
}

// ====================================================================
// split-K reduce (MLP-friendly: fully unrolled predicated split loop)
// ====================================================================
__global__ void reduce_parts(const float* __restrict__ part, int nsplit, int njobs,
                             long MN, int N,
                             const float* __restrict__ bias0,
                             const float* __restrict__ bias1, int relu,
                             float* __restrict__ of0, float* __restrict__ of1,
                             __nv_bfloat16* __restrict__ ob0) {
    long MN4 = MN >> 2;
    long total = (long)njobs * MN4;
    for (long idx = blockIdx.x * (long)blockDim.x + threadIdx.x; idx < total;
         idx += (long)gridDim.x * blockDim.x) {
        int  job = (int)(idx / MN4);
        long e4  = idx - (long)job * MN4;
        float4 acc[8];
        #pragma unroll
        for (int sp = 0; sp < 8; sp++) {
            acc[sp] = make_float4(0.f, 0.f, 0.f, 0.f);
            if (sp < nsplit)
                acc[sp] = *((const float4*)(part + ((size_t)(sp * njobs + job)) * MN) + e4);
        }
        float4 s;
        s.x = ((acc[0].x + acc[1].x) + (acc[2].x + acc[3].x)) +
              ((acc[4].x + acc[5].x) + (acc[6].x + acc[7].x));
        s.y = ((acc[0].y + acc[1].y) + (acc[2].y + acc[3].y)) +
              ((acc[4].y + acc[5].y) + (acc[6].y + acc[7].y));
        s.z = ((acc[0].z + acc[1].z) + (acc[2].z + acc[3].z)) +
              ((acc[4].z + acc[5].z) + (acc[6].z + acc[7].z));
        s.w = ((acc[0].w + acc[1].w) + (acc[2].w + acc[3].w)) +
              ((acc[4].w + acc[5].w) + (acc[6].w + acc[7].w));
        const float* bias = job ? bias1 : bias0;
        if (bias) {
            int col = (int)((e4 * 4) % N);
            s.x += bias[col]; s.y += bias[col + 1]; s.z += bias[col + 2]; s.w += bias[col + 3];
        }
        if (relu) {
            s.x = fmaxf(s.x, 0.f); s.y = fmaxf(s.y, 0.f);
            s.z = fmaxf(s.z, 0.f); s.w = fmaxf(s.w, 0.f);
        }
        if (job == 0 && ob0) {
            *(__nv_bfloat162*)(ob0 + e4 * 4)     = __floats2bfloat162_rn(s.x, s.y);
            *(__nv_bfloat162*)(ob0 + e4 * 4 + 2) = __floats2bfloat162_rn(s.z, s.w);
        } else {
            float* o = job ? of1 : of0;
            *((float4*)o + e4) = s;
        }
    }
}

// ====================================================================
// top-8: 512 warps; warp<256 -> FER matrices, else LM
// ====================================================================
__global__ void topk8_warp(const float* __restrict__ Gf, const float* __restrict__ Pf,
                           int* __restrict__ nbrf,
                           const float* __restrict__ Gl, const float* __restrict__ Pl,
                           int* __restrict__ nbrl) {
    int w = blockIdx.x * (blockDim.x >> 5) + (threadIdx.x >> 5);
    int lane = threadIdx.x & 31;
    const float* G; const float* P; int* nbr; int row;
    if (w < B_) { G = Gf; P = Pf; nbr = nbrf; row = w; }
    else        { G = Gl; P = Pl; nbr = nbrl; row = w - B_; }
    float v[8];
    #pragma unroll
    for (int t = 0; t < 8; t++) {
        int j = lane + t * 32;
        if (j == row) { v[t] = -1e30f; continue; }
        float g  = G[(size_t)row * B_ + j];
        float p1 = P[(size_t)row * B_ + j];
        float p2 = P[(size_t)j * B_ + row];
        float dg = G[(size_t)j * B_ + j];
        float dp = P[(size_t)j * B_ + j];
        v[t] = (g + p1 + p2) * rsqrtf(dg + 2.f * dp);
    }
    for (int t = 0; t < KNN; t++) {
        float bv = -1e30f; int bi = 0x7fffffff;
        #pragma unroll
        for (int q = 0; q < 8; q++) {
            int j = lane + q * 32;
            if (v[q] > bv || (v[q] == bv && j < bi)) { bv = v[q]; bi = j; }
        }
        #pragma unroll
        for (int o = 16; o; o >>= 1) {
            float ov = __shfl_xor_sync(0xffffffffu, bv, o);
            int   oi = __shfl_xor_sync(0xffffffffu, bi, o);
            if (ov > bv || (ov == bv && oi < bi)) { bv = ov; bi = oi; }
        }
        if (lane == 0) nbr[row * KNN + t] = bi;
        if (lane == (bi & 31)) v[bi >> 5] = -1e30f;
    }
}

// ====================================================================
// build H for both branches.
// blocks [0,NPAIR): FER — A/Bm from split-K partials (z = sp*2+job),
//   H[pair][k] = relu(sum_sp A_part + sum_sp Bm_part + b1) -> bf16, D=1024
// blocks [NPAIR,2*NPAIR): LM — direct fp32 A_lm/Bm_lm, D=128
// ====================================================================
__global__ void build_h_all(const float* __restrict__ part, const float* __restrict__ f_b1,
                            const int* __restrict__ nbrf, __nv_bfloat16* __restrict__ Hf,
                            const float* __restrict__ A_lm, const float* __restrict__ Bm_lm,
                            const float* __restrict__ l_b1, const int* __restrict__ nbrl,
                            __nv_bfloat16* __restrict__ Hl) {
    int blk = blockIdx.x;
    if (blk < NPAIR) {
        const long MN = (long)B_ * 1024;
        int pair = blk;
        int i = pair >> 3;
        int j = nbrf[pair];
        int k = threadIdx.x * 4;              // 256 threads * 4 = 1024
        const float4* a0 = (const float4*)(part + 0 * MN + (size_t)i * 1024 + k);
        const float4* a1 = (const float4*)(part + 2 * MN + (size_t)i * 1024 + k);
        const float4* b0 = (const float4*)(part + 1 * MN + (size_t)j * 1024 + k);
        const float4* b1p = (const float4*)(part + 3 * MN + (size_t)j * 1024 + k);
        float4 va0 = *a0, va1 = *a1, vb0 = *b0, vb1 = *b1p;
        float4 bb = *(const float4*)(f_b1 + k);
        float h0 = fmaxf(va0.x + va1.x + vb0.x + vb1.x + bb.x, 0.f);
        float h1 = fmaxf(va0.y + va1.y + vb0.y + vb1.y + bb.y, 0.f);
        float h2 = fmaxf(va0.z + va1.z + vb0.z + vb1.z + bb.z, 0.f);
        float h3 = fmaxf(va0.w + va1.w + vb0.w + vb1.w + bb.w, 0.f);
        __nv_bfloat16* hr = Hf + (size_t)pair * 1024 + k;
        *(__nv_bfloat162*)(hr)     = __floats2bfloat162_rn(h0, h1);
        *(__nv_bfloat162*)(hr + 2) = __floats2bfloat162_rn(h2, h3);
    } else {
        int pair = blk - NPAIR;
        int i = pair >> 3;
        int j = nbrl[pair];
        int t = threadIdx.x;
        if (t < 32) {
            int k = t * 4;
            float4 va = *(const float4*)(A_lm + (size_t)i * 128 + k);
            float4 vb = *(const float4*)(Bm_lm + (size_t)j * 128 + k);
            float4 bb = *(const float4*)(l_b1 + k);
            float h0 = fmaxf(va.x + vb.x + bb.x, 0.f);
            float h1 = fmaxf(va.y + vb.y + bb.y, 0.f);
            float h2 = fmaxf(va.z + vb.z + bb.z, 0.f);
            float h3 = fmaxf(va.w + vb.w + bb.w, 0.f);
            __nv_bfloat16* hr = Hl + (size_t)pair * 128 + k;
            *(__nv_bfloat162*)(hr)     = __floats2bfloat162_rn(h0, h1);
            *(__nv_bfloat162*)(hr + 2) = __floats2bfloat162_rn(h2, h3);
        }
    }
}

// ====================================================================
// fused score for both branches (4096 warps).
// warp < NPAIR: FER — H2 = relu(part0+part1+b2) summed on read, D=512
// else: LM — H2_lm direct (already relu+bias), D=64, stride 128
// ====================================================================
__global__ void score_fused(const float* __restrict__ fpart, const float* __restrict__ f_b2,
                            const float* __restrict__ f_w3, const float* __restrict__ f_b3,
                            float* __restrict__ sf,
                            const float* __restrict__ lH2, const float* __restrict__ l_w3,
                            const float* __restrict__ l_b3, float* __restrict__ sl) {
    int w = blockIdx.x * (blockDim.x >> 5) + (threadIdx.x >> 5);
    int lane = threadIdx.x & 31;
    float s = 0.f;
    if (w < NPAIR) {
        const long MN = (long)NPAIR * 512;
        const float* h0 = fpart + (size_t)w * 512;
        const float* h1 = fpart + MN + (size_t)w * 512;
        #pragma unroll
        for (int q = 0; q < 16; q++) {
            int k = lane + q * 32;
            float h = fmaxf(h0[k] + h1[k] + f_b2[k], 0.f);
            s += h * (f_w3[k] - f_w3[512 + k]);
        }
        #pragma unroll
        for (int o = 16; o; o >>= 1) s += __shfl_xor_sync(0xffffffffu, s, o);
        if (lane == 0) {
            s += f_b3[0] - f_b3[1];
            sf[w] = 1.f / (1.f + expf(-s));
        }
    } else {
        int pair = w - NPAIR;
        const float* h = lH2 + (size_t)pair * 128;
        #pragma unroll
        for (int q = 0; q < 2; q++) {
            int k = lane + q * 32;
            s += h[k] * (l_w3[k] - l_w3[64 + k]);
        }
        #pragma unroll
        for (int o = 16; o; o >>= 1) s += __shfl_xor_sync(0xffffffffu, s, o);
        if (lane == 0) {
            s += l_b3[0] - l_b3[1];
            sl[pair] = 1.f / (1.f + expf(-s));
        }
    }
}

// ====================================================================
// softmax(logits), normalize weights, combine with bank
// ====================================================================
__global__ void combine(const float* __restrict__ logits, const int* __restrict__ idx,
                        const float* __restrict__ bank,
                        const float* __restrict__ sf, const float* __restrict__ sl,
                        const int* __restrict__ nbrf, const int* __restrict__ nbrl,
                        float* __restrict__ out) {
    __shared__ float p[B_][NC];
    __shared__ float colsum[NC];
    int i = threadIdx.x;
    const float* lr = logits + i * NC;
    float m = lr[0];
    #pragma unroll
    for (int c = 1; c < NC; c++) m = fmaxf(m, lr[c]);
    float e[NC]; float ssum = 0.f;
    #pragma unroll
    for (int c = 0; c < NC; c++) { e[c] = expf(lr[c] - m); ssum += e[c]; }
    float invs = 1.f / ssum;
    #pragma unroll
    for (int c = 0; c < NC; c++) p[i][c] = e[c] * invs;
    __syncthreads();
    if (i < NC) {
        float s = 0.f;
        for (int r = 0; r < B_; r++) s += p[r][i];
        colsum[i] = s;
    }
    __syncthreads();
    float Sf = 0.f, Sl = 0.f;
    #pragma unroll
    for (int t = 0; t < KNN; t++) { Sf += sf[i * KNN + t]; Sl += sl[i * KNN + t]; }
    float df = 1.f / (Sf + EPSV), dl = 1.f / (Sl + EPSV);
    float tf[NC], tl[NC];
    #pragma unroll
    for (int c = 0; c < NC; c++) { tf[c] = 0.f; tl[c] = 0.f; }
    #pragma unroll
    for (int t = 0; t < KNN; t++) {
        int jf = nbrf[i * KNN + t]; float wf = sf[i * KNN + t] * df;
        int jl = nbrl[i * KNN + t]; float wl = sl[i * KNN + t] * dl;
        #pragma unroll
        for (int c = 0; c < NC; c++) {
            tf[c] += wf * p[jf][c];
            tl[c] += wl * p[jl][c];
        }
    }
    float ef = (EPSV / (float)B_) * df;
    float el = (EPSV / (float)B_) * dl;
    #pragma unroll
    for (int c = 0; c < NC; c++) {
        float tgt = 0.5f * (tf[c] + ef * colsum[c]) + 0.5f * (tl[c] + el * colsum[c]);
        out[i * NC + c] = bank[(size_t)idx[i] * NC + c] * 0.9f + tgt * 0.1f;
    }
}

// ====================================================================
// launcher
// ====================================================================
extern "C" void kernel_launch(void* const* d_in, const int* in_sizes, int n_in,
                              void* d_out, int out_size) {
    const float* fer_x  = (const float*)d_in[0];
    const float* lm_x   = (const float*)d_in[1];
    const float* logits = (const float*)d_in[2];
    const int*   idx    = (const int*)  d_in[3];
    const float* bank   = (const float*)d_in[4];
    const float* f_win  = (const float*)d_in[5];
    const float* f_bin  = (const float*)d_in[6];
    const float* f_w1   = (const float*)d_in[7];
    const float* f_b1   = (const float*)d_in[8];
    const float* f_w2   = (const float*)d_in[9];
    const float* f_b2   = (const float*)d_in[10];
    const float* f_w3   = (const float*)d_in[11];
    const float* f_b3   = (const float*)d_in[12];
    const float* l_win  = (const float*)d_in[13];
    const float* l_bin  = (const float*)d_in[14];
    const float* l_w1   = (const float*)d_in[15];
    const float* l_b1   = (const float*)d_in[16];
    const float* l_w2   = (const float*)d_in[17];
    const float* l_b2   = (const float*)d_in[18];
    const float* l_w3   = (const float*)d_in[19];
    const float* l_b3   = (const float*)d_in[20];
    float* out = (float*)d_out;

    Scratch* s = nullptr;
    cudaGetSymbolAddress((void**)&s, g_s);
    if (!s) return;
    cudaFuncSetAttribute(gemm_mma, cudaFuncAttributeMaxDynamicSharedMemorySize, MM_SMEM);

    // conversions + LM padding (one launch)
    convert_all<<<1024, 256>>>(f_win, f_w1, f_w2, fer_x, l_win, l_w1, lm_x, l_w2, l_b2, s);

    // --- discrete path: split-bf16 Gram matrices + merged top-8 ---
    gemm_mma<<<dim3(2, 2, 16), 256, MM_SMEM>>>(
        s->xhi_fer, s->xhi_fer, FERD, s->xhi_fer, s->xlo_fer, FERD,
        nullptr, 0, nullptr, nullptr, nullptr, s->Cpart, 2, B_, FERD);
    reduce_parts<<<128, 256>>>(s->Cpart, 8, 2, (long)B_ * B_, B_,
                               nullptr, nullptr, 0, s->G_fer, s->P_fer, nullptr);
    gemm_mma<<<dim3(2, 2, 2), 256, MM_SMEM>>>(
        s->xhi_lm, s->xhi_lm, LMD, s->xhi_lm, s->xlo_lm, LMD,
        nullptr, 0, s->G_lm, s->P_lm, nullptr, nullptr, 2, B_, LMD);
    topk8_warp<<<64, 256>>>(s->G_fer, s->P_fer, s->nbr_fer,
                            s->G_lm, s->P_lm, s->nbr_lm);

    // --- FER feats (split-K 4 -> reduce to bf16) ---
    gemm_mma<<<dim3(FERD/128, B_/128, 4), 256, MM_SMEM>>>(
        s->xhi_fer, nullptr, FERD, s->w_in_b, nullptr, FERD,
        nullptr, 0, nullptr, nullptr, nullptr, s->Cpart, 1, FERD, FERD);
    reduce_parts<<<256, 256>>>(s->Cpart, 4, 1, (long)B_ * FERD, FERD,
                               f_bin, nullptr, 0, nullptr, nullptr, s->feats_fer_b);
    // A/Bm (jobs fused, split-K 2) -> partials consumed directly by build_h_all
    gemm_mma<<<dim3(1024/128, B_/128, 4), 256, MM_SMEM>>>(
        s->feats_fer_b, s->feats_fer_b + 1024, FERD, s->w1_b, s->w1_b + 1024, FERD,
        nullptr, 0, nullptr, nullptr, nullptr, s->Cpart, 2, 1024, 1024);

    // --- LM branch GEMMs (direct outputs) ---
    gemm_mma<<<dim3(LMD/128, B_/128, 1), 256, MM_SMEM>>>(
        s->xhi_lm, nullptr, LMD, s->l_win_b, nullptr, LMD,
        l_bin, 0, nullptr, nullptr, s->feats_lm_b, nullptr, 1, LMD, LMD);
    gemm_mma<<<dim3(1, B_/128, 2), 256, MM_SMEM>>>(
        s->feats_lm_b, s->feats_lm_b + 128, LMD, s->l_w1_b, s->l_w1_b + 128, LMD,
        nullptr, 0, s->A_lm, s->Bm_lm, nullptr, nullptr, 2, 128, 128);

    // --- merged build-H (FER sums A/Bm partials inline) ---
    build_h_all<<<2 * NPAIR, 256>>>(s->Cpart, f_b1, s->nbr_fer, s->H_fer_b,
                                    s->A_lm, s->Bm_lm, l_b1, s->nbr_lm, s->H_lm_b);

    // --- H2 GEMMs ---
    gemm_mma<<<dim3(512/128, NPAIR/128, 2), 256, MM_SMEM>>>(
        s->H_fer_b, nullptr, 1024, s->w2_b, nullptr, 1024,
        nullptr, 0, nullptr, nullptr, nullptr, s->Cpart, 1, 512, 1024);
    gemm_mma<<<dim3(1, NPAIR/128, 1), 256, MM_SMEM>>>(
        s->H_lm_b, nullptr, 128, s->l_w2_pad_b, nullptr, 128,
        s->l_b2_pad, 1, s->H2_lm, nullptr, nullptr, nullptr, 1, 128, 128);

    // --- merged score (FER sums H2 partials inline) ---
    score_fused<<<512, 256>>>(s->Cpart, f_b2, f_w3, f_b3, s->score_fer,
                              s->H2_lm, l_w3, l_b3, s->score_lm);

    // --- final combine ---
    combine<<<1, B_>>>(logits, idx, bank, s->score_fer, s->score_lm,
                       s->nbr_fer, s->nbr_lm, out);
}

// round 10
// speedup vs baseline: 4.1039x; 1.4835x over previous
#include <cuda_runtime.h>
#include <cuda_bf16.h>
#include <cstdint>
#include <math.h>

#define B_      256
#define FERD    2048
#define LMD     256
#define NC      7
#define KNN     8
#define NPAIR   (B_*KNN)     // 2048
#define EPSV    1e-8f

__device__ __forceinline__ uint32_t smem_to_u32(const void* p) {
    uint32_t a;
    asm("{ .reg .u64 t; cvta.to.shared.u64 t, %1; cvt.u32.u64 %0, t; }" : "=r"(a) : "l"(p));
    return a;
}

// ====================================================================
// scratch (no allocations allowed)
// ====================================================================
struct __align__(16) Scratch {
    __nv_bfloat16 w_in_b[FERD*FERD];
    __nv_bfloat16 w1_b  [1024*FERD];
    __nv_bfloat16 w2_b  [512*1024];
    __nv_bfloat16 xhi_fer[B_*FERD];
    __nv_bfloat16 xlo_fer[B_*FERD];
    __nv_bfloat16 l_win_b[LMD*LMD];
    __nv_bfloat16 l_w1_b [128*LMD];
    __nv_bfloat16 xhi_lm [B_*LMD];
    __nv_bfloat16 xlo_lm [B_*LMD];
    __nv_bfloat16 feats_fer_b[B_*FERD];
    __nv_bfloat16 feats_lm_b [B_*LMD];
    __nv_bfloat16 H_fer_b[NPAIR*1024];
    __nv_bfloat16 H_lm_b [NPAIR*128];
    __nv_bfloat16 l_w2_pad_b[128*128];
    float         l_b2_pad[128];
    float G_fer[B_*B_], P_fer[B_*B_];
    float G_lm [B_*B_], P_lm [B_*B_];
    float A_lm [B_*128],  Bm_lm [B_*128];
    float H2_lm [NPAIR*128];
    float score_fer[NPAIR], score_lm[NPAIR];
    int   nbr_fer[NPAIR], nbr_lm[NPAIR];
    float Cpart[2*1024*1024];      // FER-chain split-K partials
    float CpartSim[16*B_*B_];      // sim-chain partials (separate: overlapped streams)
};
__device__ Scratch g_s;

// ====================================================================
// fp32 -> bf16 conversion of all tensor operands (hi/lo split for x)
// + LM w2/b2 padding (folded in)
// ====================================================================
#define CN1 (FERD*FERD)
#define CN2 (1024*FERD)
#define CN3 (512*1024)
#define CN4 (B_*FERD)
#define CN5 (LMD*LMD)
#define CN6 (128*LMD)
#define CN7 (B_*LMD)
#define CTOT (CN1+CN2+CN3+CN4+CN5+CN6+CN7)
__global__ void convert_all(const float* __restrict__ fw_in, const float* __restrict__ fw1,
                            const float* __restrict__ fw2,  const float* __restrict__ fx,
                            const float* __restrict__ lwin, const float* __restrict__ lw1,
                            const float* __restrict__ lx,
                            const float* __restrict__ lw2,  const float* __restrict__ lb2,
                            Scratch* s) {
    int total4 = CTOT / 4;
    for (int i = blockIdx.x * blockDim.x + threadIdx.x; i < total4;
         i += gridDim.x * blockDim.x) {
        int j = i * 4;
        const float* src; __nv_bfloat16* dst; __nv_bfloat16* lo = nullptr; int off;
        if      (j < CN1)                     { src=fw_in; dst=s->w_in_b;  off=j; }
        else if (j < CN1+CN2)                 { src=fw1;   dst=s->w1_b;    off=j-CN1; }
        else if (j < CN1+CN2+CN3)             { src=fw2;   dst=s->w2_b;    off=j-CN1-CN2; }
        else if (j < CN1+CN2+CN3+CN4)         { src=fx;    dst=s->xhi_fer; lo=s->xlo_fer;
                                                off=j-CN1-CN2-CN3; }
        else if (j < CN1+CN2+CN3+CN4+CN5)     { src=lwin;  dst=s->l_win_b; off=j-CN1-CN2-CN3-CN4; }
        else if (j < CN1+CN2+CN3+CN4+CN5+CN6) { src=lw1;   dst=s->l_w1_b;  off=j-CN1-CN2-CN3-CN4-CN5; }
        else                                  { src=lx;    dst=s->xhi_lm;  lo=s->xlo_lm;
                                                off=j-CN1-CN2-CN3-CN4-CN5-CN6; }
        float4 v = *(const float4*)(src + off);
        __nv_bfloat16 h0 = __float2bfloat16(v.x), h1 = __float2bfloat16(v.y);
        __nv_bfloat16 h2 = __float2bfloat16(v.z), h3 = __float2bfloat16(v.w);
        *(__nv_bfloat162*)(dst + off)     = __nv_bfloat162(h0, h1);
        *(__nv_bfloat162*)(dst + off + 2) = __nv_bfloat162(h2, h3);
        if (lo) {
            *(__nv_bfloat162*)(lo + off) = __nv_bfloat162(
                __float2bfloat16(v.x - __bfloat162float(h0)),
                __float2bfloat16(v.y - __bfloat162float(h1)));
            *(__nv_bfloat162*)(lo + off + 2) = __nv_bfloat162(
                __float2bfloat16(v.z - __bfloat162float(h2)),
                __float2bfloat16(v.w - __bfloat162float(h3)));
        }
    }
    int t = blockIdx.x * blockDim.x + threadIdx.x;
    if (t < 128 * 128) {
        int r = t >> 7, c = t & 127;
        s->l_w2_pad_b[t] = __float2bfloat16(r < 64 ? lw2[r * 128 + c] : 0.f);
    }
    if (t < 128) s->l_b2_pad[t] = (t < 64) ? lb2[t] : 0.f;
}

// ====================================================================
// bf16 HMMA GEMM with job-fusion (grid.z) and split-K partial output.
// ====================================================================
#define MM_LDS   72
#define MM_ATILE (128*MM_LDS*2)
#define MM_BUF   (2*MM_ATILE)
#define MM_SMEM  (3*MM_BUF)          // 110592 bytes

__global__ void __launch_bounds__(256)
gemm_mma(const __nv_bfloat16* __restrict__ A0, const __nv_bfloat16* __restrict__ A1, int lda,
         const __nv_bfloat16* __restrict__ B0, const __nv_bfloat16* __restrict__ B1, int ldb,
         const float* __restrict__ bias, int relu,
         float* __restrict__ Cf0, float* __restrict__ Cf1,
         __nv_bfloat16* __restrict__ Cb0,
         float* __restrict__ Cpart,
         int njobs, int N, int K)
{
    extern __shared__ char smem[];
    uint32_t sb = smem_to_u32(smem);
    int tid = threadIdx.x;
    int lane = tid & 31, warp = tid >> 5;
    int wm = warp >> 2, wn = warp & 3;
    int m0 = blockIdx.y * 128, n0 = blockIdx.x * 128;

    int z = blockIdx.z;
    int job   = (njobs == 2) ? (z & 1) : 0;
    int split = (njobs == 2) ? (z >> 1) : z;
    int nsplit = gridDim.z / njobs;
    int Ksplit = K / nsplit;
    int kbase = split * Ksplit;
    int nk = Ksplit >> 6;

    const __nv_bfloat16* A = job ? A1 : A0;
    const __nv_bfloat16* B = job ? B1 : B0;

    float acc[4][4][4];
    #pragma unroll
    for (int i = 0; i < 4; i++)
        #pragma unroll
        for (int j = 0; j < 4; j++)
            #pragma unroll
            for (int q = 0; q < 4; q++) acc[i][j][q] = 0.f;

    auto issue = [&](int kt) {
        int st = kt % 3;
        uint32_t base = sb + st * MM_BUF;
        int k0 = kbase + kt * 64;
        #pragma unroll
        for (int u = 0; u < 4; u++) {
            int cc = tid * 4 + u;
            int row = cc >> 3;
            int col = (cc & 7) * 8;
            uint32_t da = base + (uint32_t)(row * MM_LDS + col) * 2;
            const __nv_bfloat16* ga = A + (size_t)(m0 + row) * lda + k0 + col;
            asm volatile("cp.async.cg.shared.global [%0], [%1], 16;" :: "r"(da), "l"(ga));
            const __nv_bfloat16* gb = B + (size_t)(n0 + row) * ldb + k0 + col;
            asm volatile("cp.async.cg.shared.global [%0], [%1], 16;"
                         :: "r"(da + MM_ATILE), "l"(gb));
        }
        asm volatile("cp.async.commit_group;" ::: "memory");
    };

    issue(0);
    if (nk > 1) issue(1);
    for (int kt = 0; kt < nk; kt++) {
        if (kt + 2 < nk) {
            issue(kt + 2);
            asm volatile("cp.async.wait_group 2;" ::: "memory");
        } else if (kt + 1 < nk) {
            asm volatile("cp.async.wait_group 1;" ::: "memory");
        } else {
            asm volatile("cp.async.wait_group 0;" ::: "memory");
        }
        __syncthreads();

        uint32_t aBase = sb + (kt % 3) * MM_BUF;
        uint32_t bBase = aBase + MM_ATILE;
        #pragma unroll
        for (int ks = 0; ks < 4; ks++) {
            int k = ks * 16;
            uint32_t af[4][4];
            #pragma unroll
            for (int im = 0; im < 4; im++) {
                int row = wm * 64 + im * 16 + (lane & 15);
                int kg = (lane >> 4) * 8;
                uint32_t addr = aBase + (uint32_t)(row * MM_LDS + k + kg) * 2;
                asm volatile("ldmatrix.sync.aligned.m8n8.x4.shared.b16 {%0,%1,%2,%3}, [%4];"
                             : "=r"(af[im][0]), "=r"(af[im][1]),
                               "=r"(af[im][2]), "=r"(af[im][3])
                             : "r"(addr));
            }
            uint32_t bf[4][2];
            #pragma unroll
            for (int in = 0; in < 4; in++) {
                int l = lane & 15;
                int n = wn * 32 + in * 8 + (l & 7);
                int kg = (l >> 3) * 8;
                uint32_t addr = bBase + (uint32_t)(n * MM_LDS + k + kg) * 2;
                asm volatile("ldmatrix.sync.aligned.m8n8.x2.shared.b16 {%0,%1}, [%2];"
                             : "=r"(bf[in][0]), "=r"(bf[in][1])
                             : "r"(addr));
            }
            #pragma unroll
            for (int im = 0; im < 4; im++)
                #pragma unroll
                for (int in = 0; in < 4; in++) {
                    asm volatile(
                        "mma.sync.aligned.m16n8k16.row.col.f32.bf16.bf16.f32 "
                        "{%0,%1,%2,%3}, {%4,%5,%6,%7}, {%8,%9}, {%0,%1,%2,%3};"
                        : "+f"(acc[im][in][0]), "+f"(acc[im][in][1]),
                          "+f"(acc[im][in][2]), "+f"(acc[im][in][3])
                        : "r"(af[im][0]), "r"(af[im][1]), "r"(af[im][2]), "r"(af[im][3]),
                          "r"(bf[in][0]), "r"(bf[in][1]));
                }
        }
        __syncthreads();
    }

    if (Cpart) {
        size_t MN = (size_t)gridDim.y * 128 * N;
        float* cp = Cpart + (size_t)z * MN;
        #pragma unroll
        for (int im = 0; im < 4; im++) {
            int m = m0 + wm * 64 + im * 16 + (lane >> 2);
            #pragma unroll
            for (int in = 0; in < 4; in++) {
                int n = n0 + wn * 32 + in * 8 + (lane & 3) * 2;
                *(float2*)(cp + (size_t)m * N + n) =
                    make_float2(acc[im][in][0], acc[im][in][1]);
                *(float2*)(cp + (size_t)(m + 8) * N + n) =
                    make_float2(acc[im][in][2], acc[im][in][3]);
            }
        }
        return;
    }
    float* Cf = job ? Cf1 : Cf0;
    #pragma unroll
    for (int im = 0; im < 4; im++) {
        int m = m0 + wm * 64 + im * 16 + (lane >> 2);
        #pragma unroll
        for (int in = 0; in < 4; in++) {
            int n = n0 + wn * 32 + in * 8 + (lane & 3) * 2;
            float b0 = bias ? bias[n]     : 0.f;
            float b1 = bias ? bias[n + 1] : 0.f;
            float v00 = acc[im][in][0] + b0, v01 = acc[im][in][1] + b1;
            float v10 = acc[im][in][2] + b0, v11 = acc[im][in][3] + b1;
            if (relu) {
                v00 = fmaxf(v00, 0.f); v01 = fmaxf(v01, 0.f);
                v10 = fmaxf(v10, 0.f); v11 = fmaxf(v11, 0.f);
            }
            if (Cb0) {
                *(__nv_bfloat162*)(Cb0 + (size_t)m * N + n) =
                    __floats2bfloat162_rn(v00, v01);
                *(__nv_bfloat162*)(Cb0 + (size_t)(m + 8) * N + n) =
                    __floats2bfloat162_rn(v10, v11);
            } else {
                *(float2*)(Cf + (size_t)m * N + n)       = make_float2(v00, v01);
                *(float2*)(Cf + (size_t)(m + 8) * N + n) = make_float2(v10, v11);
            }
        }
    }
}

// ====================================================================
// split-K reduce (fully unrolled predicated split loop)
// ====================================================================
__global__ void reduce_parts(const float* __restrict__ part, int nsplit, int njobs,
                             long MN, int N,
                             const float* __restrict__ bias0,
                             const float* __restrict__ bias1, int relu,
                             float* __restrict__ of0, float* __restrict__ of1,
                             __nv_bfloat16* __restrict__ ob0) {
    long MN4 = MN >> 2;
    long total = (long)njobs * MN4;
    for (long idx = blockIdx.x * (long)blockDim.x + threadIdx.x; idx < total;
         idx += (long)gridDim.x * blockDim.x) {
        int  job = (int)(idx / MN4);
        long e4  = idx - (long)job * MN4;
        float4 acc[8];
        #pragma unroll
        for (int sp = 0; sp < 8; sp++) {
            acc[sp] = make_float4(0.f, 0.f, 0.f, 0.f);
            if (sp < nsplit)
                acc[sp] = *((const float4*)(part + ((size_t)(sp * njobs + job)) * MN) + e4);
        }
        float4 s;
        s.x = ((acc[0].x + acc[1].x) + (acc[2].x + acc[3].x)) +
              ((acc[4].x + acc[5].x) + (acc[6].x + acc[7].x));
        s.y = ((acc[0].y + acc[1].y) + (acc[2].y + acc[3].y)) +
              ((acc[4].y + acc[5].y) + (acc[6].y + acc[7].y));
        s.z = ((acc[0].z + acc[1].z) + (acc[2].z + acc[3].z)) +
              ((acc[4].z + acc[5].z) + (acc[6].z + acc[7].z));
        s.w = ((acc[0].w + acc[1].w) + (acc[2].w + acc[3].w)) +
              ((acc[4].w + acc[5].w) + (acc[6].w + acc[7].w));
        const float* bias = job ? bias1 : bias0;
        if (bias) {
            int col = (int)((e4 * 4) % N);
            s.x += bias[col]; s.y += bias[col + 1]; s.z += bias[col + 2]; s.w += bias[col + 3];
        }
        if (relu) {
            s.x = fmaxf(s.x, 0.f); s.y = fmaxf(s.y, 0.f);
            s.z = fmaxf(s.z, 0.f); s.w = fmaxf(s.w, 0.f);
        }
        if (job == 0 && ob0) {
            *(__nv_bfloat162*)(ob0 + e4 * 4)     = __floats2bfloat162_rn(s.x, s.y);
            *(__nv_bfloat162*)(ob0 + e4 * 4 + 2) = __floats2bfloat162_rn(s.z, s.w);
        } else {
            float* o = job ? of1 : of0;
            *((float4*)o + e4) = s;
        }
    }
}

// ====================================================================
// top-8: 512 warps; warp<256 -> FER matrices, else LM
// ====================================================================
__global__ void topk8_warp(const float* __restrict__ Gf, const float* __restrict__ Pf,
                           int* __restrict__ nbrf,
                           const float* __restrict__ Gl, const float* __restrict__ Pl,
                           int* __restrict__ nbrl) {
    int w = blockIdx.x * (blockDim.x >> 5) + (threadIdx.x >> 5);
    int lane = threadIdx.x & 31;
    const float* G; const float* P; int* nbr; int row;
    if (w < B_) { G = Gf; P = Pf; nbr = nbrf; row = w; }
    else        { G = Gl; P = Pl; nbr = nbrl; row = w - B_; }
    float v[8];
    #pragma unroll
    for (int t = 0; t < 8; t++) {
        int j = lane + t * 32;
        if (j == row) { v[t] = -1e30f; continue; }
        float g  = G[(size_t)row * B_ + j];
        float p1 = P[(size_t)row * B_ + j];
        float p2 = P[(size_t)j * B_ + row];
        float dg = G[(size_t)j * B_ + j];
        float dp = P[(size_t)j * B_ + j];
        v[t] = (g + p1 + p2) * rsqrtf(dg + 2.f * dp);
    }
    for (int t = 0; t < KNN; t++) {
        float bv = -1e30f; int bi = 0x7fffffff;
        #pragma unroll
        for (int q = 0; q < 8; q++) {
            int j = lane + q * 32;
            if (v[q] > bv || (v[q] == bv && j < bi)) { bv = v[q]; bi = j; }
        }
        #pragma unroll
        for (int o = 16; o; o >>= 1) {
            float ov = __shfl_xor_sync(0xffffffffu, bv, o);
            int   oi = __shfl_xor_sync(0xffffffffu, bi, o);
            if (ov > bv || (ov == bv && oi < bi)) { bv = ov; bi = oi; }
        }
        if (lane == 0) nbr[row * KNN + t] = bi;
        if (lane == (bi & 31)) v[bi >> 5] = -1e30f;
    }
}

// ====================================================================
// build H for both branches (FER sums A/Bm split-K partials inline)
// ====================================================================
__global__ void build_h_all(const float* __restrict__ part, const float* __restrict__ f_b1,
                            const int* __restrict__ nbrf, __nv_bfloat16* __restrict__ Hf,
                            const float* __restrict__ A_lm, const float* __restrict__ Bm_lm,
                            const float* __restrict__ l_b1, const int* __restrict__ nbrl,
                            __nv_bfloat16* __restrict__ Hl) {
    int blk = blockIdx.x;
    if (blk < NPAIR) {
        const long MN = (long)B_ * 1024;
        int pair = blk;
        int i = pair >> 3;
        int j = nbrf[pair];
        int k = threadIdx.x * 4;
        const float4* a0 = (const float4*)(part + 0 * MN + (size_t)i * 1024 + k);
        const float4* a1 = (const float4*)(part + 2 * MN + (size_t)i * 1024 + k);
        const float4* b0 = (const float4*)(part + 1 * MN + (size_t)j * 1024 + k);
        const float4* b1p = (const float4*)(part + 3 * MN + (size_t)j * 1024 + k);
        float4 va0 = *a0, va1 = *a1, vb0 = *b0, vb1 = *b1p;
        float4 bb = *(const float4*)(f_b1 + k);
        float h0 = fmaxf(va0.x + va1.x + vb0.x + vb1.x + bb.x, 0.f);
        float h1 = fmaxf(va0.y + va1.y + vb0.y + vb1.y + bb.y, 0.f);
        float h2 = fmaxf(va0.z + va1.z + vb0.z + vb1.z + bb.z, 0.f);
        float h3 = fmaxf(va0.w + va1.w + vb0.w + vb1.w + bb.w, 0.f);
        __nv_bfloat16* hr = Hf + (size_t)pair * 1024 + k;
        *(__nv_bfloat162*)(hr)     = __floats2bfloat162_rn(h0, h1);
        *(__nv_bfloat162*)(hr + 2) = __floats2bfloat162_rn(h2, h3);
    } else {
        int pair = blk - NPAIR;
        int i = pair >> 3;
        int j = nbrl[pair];
        int t = threadIdx.x;
        if (t < 32) {
            int k = t * 4;
            float4 va = *(const float4*)(A_lm + (size_t)i * 128 + k);
            float4 vb = *(const float4*)(Bm_lm + (size_t)j * 128 + k);
            float4 bb = *(const float4*)(l_b1 + k);
            float h0 = fmaxf(va.x + vb.x + bb.x, 0.f);
            float h1 = fmaxf(va.y + vb.y + bb.y, 0.f);
            float h2 = fmaxf(va.z + vb.z + bb.z, 0.f);
            float h3 = fmaxf(va.w + vb.w + bb.w, 0.f);
            __nv_bfloat16* hr = Hl + (size_t)pair * 128 + k;
            *(__nv_bfloat162*)(hr)     = __floats2bfloat162_rn(h0, h1);
            *(__nv_bfloat162*)(hr + 2) = __floats2bfloat162_rn(h2, h3);
        }
    }
}

// ====================================================================
// fused score for both branches (FER sums H2 partials inline)
// ====================================================================
__global__ void score_fused(const float* __restrict__ fpart, const float* __restrict__ f_b2,
                            const float* __restrict__ f_w3, const float* __restrict__ f_b3,
                            float* __restrict__ sf,
                            const float* __restrict__ lH2, const float* __restrict__ l_w3,
                            const float* __restrict__ l_b3, float* __restrict__ sl) {
    int w = blockIdx.x * (blockDim.x >> 5) + (threadIdx.x >> 5);
    int lane = threadIdx.x & 31;
    float s = 0.f;
    if (w < NPAIR) {
        const long MN = (long)NPAIR * 512;
        const float* h0 = fpart + (size_t)w * 512;
        const float* h1 = fpart + MN + (size_t)w * 512;
        #pragma unroll
        for (int q = 0; q < 16; q++) {
            int k = lane + q * 32;
            float h = fmaxf(h0[k] + h1[k] + f_b2[k], 0.f);
            s += h * (f_w3[k] - f_w3[512 + k]);
        }
        #pragma unroll
        for (int o = 16; o; o >>= 1) s += __shfl_xor_sync(0xffffffffu, s, o);
        if (lane == 0) {
            s += f_b3[0] - f_b3[1];
            sf[w] = 1.f / (1.f + expf(-s));
        }
    } else {
        int pair = w - NPAIR;
        const float* h = lH2 + (size_t)pair * 128;
        #pragma unroll
        for (int q = 0; q < 2; q++) {
            int k = lane + q * 32;
            s += h[k] * (l_w3[k] - l_w3[64 + k]);
        }
        #pragma unroll
        for (int o = 16; o; o >>= 1) s += __shfl_xor_sync(0xffffffffu, s, o);
        if (lane == 0) {
            s += l_b3[0] - l_b3[1];
            sl[pair] = 1.f / (1.f + expf(-s));
        }
    }
}

// ====================================================================
// softmax(logits), normalize weights, combine with bank
// ====================================================================
__global__ void combine(const float* __restrict__ logits, const int* __restrict__ idx,
                        const float* __restrict__ bank,
                        const float* __restrict__ sf, const float* __restrict__ sl,
                        const int* __restrict__ nbrf, const int* __restrict__ nbrl,
                        float* __restrict__ out) {
    __shared__ float p[B_][NC];
    __shared__ float colsum[NC];
    int i = threadIdx.x;
    const float* lr = logits + i * NC;
    float m = lr[0];
    #pragma unroll
    for (int c = 1; c < NC; c++) m = fmaxf(m, lr[c]);
    float e[NC]; float ssum = 0.f;
    #pragma unroll
    for (int c = 0; c < NC; c++) { e[c] = expf(lr[c] - m); ssum += e[c]; }
    float invs = 1.f / ssum;
    #pragma unroll
    for (int c = 0; c < NC; c++) p[i][c] = e[c] * invs;
    __syncthreads();
    if (i < NC) {
        float s = 0.f;
        for (int r = 0; r < B_; r++) s += p[r][i];
        colsum[i] = s;
    }
    __syncthreads();
    float Sf = 0.f, Sl = 0.f;
    #pragma unroll
    for (int t = 0; t < KNN; t++) { Sf += sf[i * KNN + t]; Sl += sl[i * KNN + t]; }
    float df = 1.f / (Sf + EPSV), dl = 1.f / (Sl + EPSV);
    float tf[NC], tl[NC];
    #pragma unroll
    for (int c = 0; c < NC; c++) { tf[c] = 0.f; tl[c] = 0.f; }
    #pragma unroll
    for (int t = 0; t < KNN; t++) {
        int jf = nbrf[i * KNN + t]; float wf = sf[i * KNN + t] * df;
        int jl = nbrl[i * KNN + t]; float wl = sl[i * KNN + t] * dl;
        #pragma unroll
        for (int c = 0; c < NC; c++) {
            tf[c] += wf * p[jf][c];
            tl[c] += wl * p[jl][c];
        }
    }
    float ef = (EPSV / (float)B_) * df;
    float el = (EPSV / (float)B_) * dl;
    #pragma unroll
    for (int c = 0; c < NC; c++) {
        float tgt = 0.5f * (tf[c] + ef * colsum[c]) + 0.5f * (tl[c] + el * colsum[c]);
        out[i * NC + c] = bank[(size_t)idx[i] * NC + c] * 0.9f + tgt * 0.1f;
    }
}

// ====================================================================
// launcher — fork/join DAG across 3 side streams (graph-capturable).
// Streams/events created ONCE on first (uncaptured) call; the capture
// call performs only launches + event record/wait.
// ====================================================================
extern "C" void kernel_launch(void* const* d_in, const int* in_sizes, int n_in,
                              void* d_out, int out_size) {
    const float* fer_x  = (const float*)d_in[0];
    const float* lm_x   = (const float*)d_in[1];
    const float* logits = (const float*)d_in[2];
    const int*   idx    = (const int*)  d_in[3];
    const float* bank   = (const float*)d_in[4];
    const float* f_win  = (const float*)d_in[5];
    const float* f_bin  = (const float*)d_in[6];
    const float* f_w1   = (const float*)d_in[7];
    const float* f_b1   = (const float*)d_in[8];
    const float* f_w2   = (const float*)d_in[9];
    const float* f_b2   = (const float*)d_in[10];
    const float* f_w3   = (const float*)d_in[11];
    const float* f_b3   = (const float*)d_in[12];
    const float* l_win  = (const float*)d_in[13];
    const float* l_bin  = (const float*)d_in[14];
    const float* l_w1   = (const float*)d_in[15];
    const float* l_b1   = (const float*)d_in[16];
    const float* l_w2   = (const float*)d_in[17];
    const float* l_b2   = (const float*)d_in[18];
    const float* l_w3   = (const float*)d_in[19];
    const float* l_b3   = (const float*)d_in[20];
    float* out = (float*)d_out;

    Scratch* s = nullptr;
    cudaGetSymbolAddress((void**)&s, g_s);
    if (!s) return;

    // one-time host-side resource setup (runs on the uncaptured correctness call)
    struct Res {
        cudaStream_t s1, s2, s3;
        cudaEvent_t e0, eS2, eT, eL3, eBH, eLH;
        Res() {
            cudaStreamCreateWithFlags(&s1, cudaStreamNonBlocking);
            cudaStreamCreateWithFlags(&s2, cudaStreamNonBlocking);
            cudaStreamCreateWithFlags(&s3, cudaStreamNonBlocking);
            cudaEventCreateWithFlags(&e0,  cudaEventDisableTiming);
            cudaEventCreateWithFlags(&eS2, cudaEventDisableTiming);
            cudaEventCreateWithFlags(&eT,  cudaEventDisableTiming);
            cudaEventCreateWithFlags(&eL3, cudaEventDisableTiming);
            cudaEventCreateWithFlags(&eBH, cudaEventDisableTiming);
            cudaEventCreateWithFlags(&eLH, cudaEventDisableTiming);
            cudaFuncSetAttribute(gemm_mma,
                cudaFuncAttributeMaxDynamicSharedMemorySize, MM_SMEM);
        }
    };
    static Res r;
    cudaStream_t L = 0;

    // root: conversions
    convert_all<<<1024, 256, 0, L>>>(f_win, f_w1, f_w2, fer_x, l_win, l_w1, lm_x,
                                     l_w2, l_b2, s);
    cudaEventRecord(r.e0, L);

    // branch s1: FER sim -> reduce -> (wait LM sim) -> topk
    cudaStreamWaitEvent(r.s1, r.e0, 0);
    gemm_mma<<<dim3(2, 2, 16), 256, MM_SMEM, r.s1>>>(
        s->xhi_fer, s->xhi_fer, FERD, s->xhi_fer, s->xlo_fer, FERD,
        nullptr, 0, nullptr, nullptr, nullptr, s->CpartSim, 2, B_, FERD);
    reduce_parts<<<128, 256, 0, r.s1>>>(s->CpartSim, 8, 2, (long)B_ * B_, B_,
                                        nullptr, nullptr, 0, s->G_fer, s->P_fer, nullptr);
    // branch s2: LM sim
    cudaStreamWaitEvent(r.s2, r.e0, 0);
    gemm_mma<<<dim3(2, 2, 2), 256, MM_SMEM, r.s2>>>(
        s->xhi_lm, s->xhi_lm, LMD, s->xhi_lm, s->xlo_lm, LMD,
        nullptr, 0, s->G_lm, s->P_lm, nullptr, nullptr, 2, B_, LMD);
    cudaEventRecord(r.eS2, r.s2);
    cudaStreamWaitEvent(r.s1, r.eS2, 0);
    topk8_warp<<<64, 256, 0, r.s1>>>(s->G_fer, s->P_fer, s->nbr_fer,
                                     s->G_lm, s->P_lm, s->nbr_lm);
    cudaEventRecord(r.eT, r.s1);

    // branch s3: LM MLP (feats -> A/Bm)
    cudaStreamWaitEvent(r.s3, r.e0, 0);
    gemm_mma<<<dim3(LMD/128, B_/128, 1), 256, MM_SMEM, r.s3>>>(
        s->xhi_lm, nullptr, LMD, s->l_win_b, nullptr, LMD,
        l_bin, 0, nullptr, nullptr, s->feats_lm_b, nullptr, 1, LMD, LMD);
    gemm_mma<<<dim3(1, B_/128, 2), 256, MM_SMEM, r.s3>>>(
        s->feats_lm_b, s->feats_lm_b + 128, LMD, s->l_w1_b, s->l_w1_b + 128, LMD,
        nullptr, 0, s->A_lm, s->Bm_lm, nullptr, nullptr, 2, 128, 128);
    cudaEventRecord(r.eL3, r.s3);

    // main stream: FER MLP (feats -> reduce -> A/Bm)
    gemm_mma<<<dim3(FERD/128, B_/128, 4), 256, MM_SMEM, L>>>(
        s->xhi_fer, nullptr, FERD, s->w_in_b, nullptr, FERD,
        nullptr, 0, nullptr, nullptr, nullptr, s->Cpart, 1, FERD, FERD);
    reduce_parts<<<256, 256, 0, L>>>(s->Cpart, 4, 1, (long)B_ * FERD, FERD,
                                     f_bin, nullptr, 0, nullptr, nullptr, s->feats_fer_b);
    gemm_mma<<<dim3(1024/128, B_/128, 4), 256, MM_SMEM, L>>>(
        s->feats_fer_b, s->feats_fer_b + 1024, FERD, s->w1_b, s->w1_b + 1024, FERD,
        nullptr, 0, nullptr, nullptr, nullptr, s->Cpart, 2, 1024, 1024);

    // join: build H needs topk (eT), LM A/Bm (eL3), FER A/Bm (in-order on L)
    cudaStreamWaitEvent(L, r.eT, 0);
    cudaStreamWaitEvent(L, r.eL3, 0);
    build_h_all<<<2 * NPAIR, 256, 0, L>>>(s->Cpart, f_b1, s->nbr_fer, s->H_fer_b,
                                          s->A_lm, s->Bm_lm, l_b1, s->nbr_lm, s->H_lm_b);
    cudaEventRecord(r.eBH, L);

    // FER H2 on L; LM H2 on s3 (both depend on build_h)
    gemm_mma<<<dim3(512/128, NPAIR/128, 2), 256, MM_SMEM, L>>>(
        s->H_fer_b, nullptr, 1024, s->w2_b, nullptr, 1024,
        nullptr, 0, nullptr, nullptr, nullptr, s->Cpart, 1, 512, 1024);
    cudaStreamWaitEvent(r.s3, r.eBH, 0);
    gemm_mma<<<dim3(1, NPAIR/128, 1), 256, MM_SMEM, r.s3>>>(
        s->H_lm_b, nullptr, 128, s->l_w2_pad_b, nullptr, 128,
        s->l_b2_pad, 1, s->H2_lm, nullptr, nullptr, nullptr, 1, 128, 128);
    cudaEventRecord(r.eLH, r.s3);

    // join: score needs FER H2 (L in-order) + LM H2 (eLH)
    cudaStreamWaitEvent(L, r.eLH, 0);
    score_fused<<<512, 256, 0, L>>>(s->Cpart, f_b2, f_w3, f_b3, s->score_fer,
                                    s->H2_lm, l_w3, l_b3, s->score_lm);
    combine<<<1, B_, 0, L>>>(logits, idx, bank, s->score_fer, s->score_lm,
                             s->nbr_fer, s->nbr_lm, out);
}